// round 5
// baseline (speedup 1.0000x reference)
#include <cuda_runtime.h>
#include <cuda_bf16.h>
#include <cstdint>
#include <math.h>

// ---------------- problem constants ----------------
constexpr int NB     = 2;
constexpr int NC     = 256;     // channels (= QK)
constexpr int NHW    = 16384;   // H*W
constexpr int NS     = 256;     // superpixels
constexpr int NT     = 128;     // top-k
constexpr int NHEADS = 8;
constexpr int NDH    = 32;      // head dim
constexpr int MTOT   = 768;     // q(256) + k(256) + v(256)
constexpr float EPSV      = 1e-5f;
constexpr float ATT_SCALE = 0.17677669529663687f;  // 1/sqrt(32)

// ---------------- scratch (device globals; no allocations allowed) ----------
__device__ float  g_yt [(size_t)NB * NHW * MTOT];        // qkv, n-major fp32
__device__ float  g_acc[(size_t)NB * NHW * NC];          // output accumulator (n-major)
__device__ float  g_sims[NB * NS * NT];
__device__ int    g_idx [NB * NS * NT];
__device__ float2 g_stat[NB * NHW];                      // (mu, inv) per pixel
__device__ __nv_bfloat16 g_xh[(size_t)NB * NHW * NC];    // ln(x) hi, [b][n][c]
__device__ __nv_bfloat16 g_xl[(size_t)NB * NHW * NC];    // ln(x) lo
__device__ __nv_bfloat16 g_wh[MTOT * NC];                // stacked W hi
__device__ __nv_bfloat16 g_wl[MTOT * NC];                // stacked W lo

// ---------------- warp-MMA helpers (baseline PTX, valid on compute_103) ----
__device__ __forceinline__ uint32_t smem_u32(const void* p) {
    uint32_t a;
    asm("{ .reg .u64 t; cvta.to.shared.u64 t, %1; cvt.u32.u64 %0, t; }" : "=r"(a) : "l"(p));
    return a;
}
__device__ __forceinline__ void ldsm4(uint32_t* r, uint32_t addr) {
    asm volatile("ldmatrix.sync.aligned.m8n8.x4.shared.b16 {%0,%1,%2,%3}, [%4];"
                 : "=r"(r[0]), "=r"(r[1]), "=r"(r[2]), "=r"(r[3]) : "r"(addr));
}
__device__ __forceinline__ void mma16816(float* d, const uint32_t* a, const uint32_t* b) {
    asm volatile("mma.sync.aligned.m16n8k16.row.col.f32.bf16.bf16.f32 "
                 "{%0,%1,%2,%3}, {%4,%5,%6,%7}, {%8,%9}, {%0,%1,%2,%3};"
                 : "+f"(d[0]), "+f"(d[1]), "+f"(d[2]), "+f"(d[3])
                 : "r"(a[0]), "r"(a[1]), "r"(a[2]), "r"(a[3]), "r"(b[0]), "r"(b[1]));
}

// =====================================================================
// Kernel 1a: LayerNorm statistics per pixel (coalesced over n).
// =====================================================================
__global__ void __launch_bounds__(256) ln_stats_kernel(const float* __restrict__ x) {
    int p = blockIdx.x * blockDim.x + threadIdx.x;
    int b = p / NHW;
    int n = p - b * NHW;
    const float* xb = x + (size_t)b * NC * NHW + n;
    float s = 0.f, ss = 0.f;
#pragma unroll 8
    for (int c = 0; c < NC; c++) {
        float v = xb[(size_t)c * NHW];
        s += v; ss += v * v;
    }
    float mu  = s * (1.0f / NC);
    float var = ss * (1.0f / NC) - mu * mu;
    g_stat[p] = make_float2(mu, rsqrtf(var + EPSV));
}

// =====================================================================
// Kernel 1b: normalize + transpose to [b][n][c] + bf16 hi/lo split.
// =====================================================================
__global__ void __launch_bounds__(256) xsplit_kernel(const float* __restrict__ x,
                                                     const float* __restrict__ lw,
                                                     const float* __restrict__ lb) {
    __shared__ float tile[32][33];
    const int b  = blockIdx.z;
    const int n0 = blockIdx.x * 32;
    const int c0 = blockIdx.y * 32;
    const int tx = threadIdx.x, ty = threadIdx.y;
#pragma unroll
    for (int j = 0; j < 32; j += 8)
        tile[ty + j][tx] = x[((size_t)b * NC + c0 + ty + j) * NHW + n0 + tx];
    __syncthreads();
    const float w = lw[c0 + tx], bi = lb[c0 + tx];
#pragma unroll
    for (int j = 0; j < 32; j += 8) {
        int n = n0 + ty + j;
        float2 st = g_stat[b * NHW + n];
        float v = (tile[tx][ty + j] - st.x) * st.y * w + bi;
        __nv_bfloat16 hi = __float2bfloat16_rn(v);
        __nv_bfloat16 lo = __float2bfloat16_rn(v - __bfloat162float(hi));
        size_t o = ((size_t)b * NHW + n) * NC + c0 + tx;
        g_xh[o] = hi;
        g_xl[o] = lo;
    }
}

// =====================================================================
// Kernel 1c: split stacked W (wq;wk;wv) into bf16 hi/lo.
// =====================================================================
__global__ void __launch_bounds__(256) wsplit_kernel(const float* __restrict__ wq,
                                                     const float* __restrict__ wk,
                                                     const float* __restrict__ wv) {
    int m = blockIdx.x, c = threadIdx.x;
    const float* src = (m < 256) ? (wq + (size_t)m * NC)
                     : (m < 512) ? (wk + (size_t)(m - 256) * NC)
                                 : (wv + (size_t)(m - 512) * NC);
    float v = src[c];
    __nv_bfloat16 hi = __float2bfloat16_rn(v);
    __nv_bfloat16 lo = __float2bfloat16_rn(v - __bfloat162float(hi));
    g_wh[(size_t)m * NC + c] = hi;
    g_wl[(size_t)m * NC + c] = lo;
}

// =====================================================================
// Kernel 2: exact top-128 per affinity row via radix select.
// =====================================================================
__device__ __forceinline__ unsigned f2k(float f) {
    unsigned u = __float_as_uint(f);
    return (u & 0x80000000u) ? ~u : (u | 0x80000000u);
}

__global__ void __launch_bounds__(256) topk_kernel(const float* __restrict__ aff) {
    const int row = blockIdx.x;
    const float* a = aff + (size_t)row * NHW;

    __shared__ unsigned hist[256];
    __shared__ unsigned sh_digit, sh_rem;
    __shared__ int cnt_gt, eqcnt;
    __shared__ int eqlist[64];

    unsigned prefix = 0, prefmask = 0;
    unsigned rem = NT;

    for (int shift = 24; shift >= 0; shift -= 8) {
        for (int i = threadIdx.x; i < 256; i += blockDim.x) hist[i] = 0;
        __syncthreads();
        for (int i = threadIdx.x; i < NHW; i += blockDim.x) {
            unsigned key = f2k(a[i]);
            if ((key & prefmask) == prefix)
                atomicAdd(&hist[(key >> shift) & 255u], 1u);
        }
        __syncthreads();
        if (threadIdx.x == 0) {
            unsigned r = rem;
            int d = 255;
            for (; d > 0; d--) {
                unsigned c = hist[d];
                if (c >= r) break;
                r -= c;
            }
            sh_digit = (unsigned)d;
            sh_rem = r;
        }
        __syncthreads();
        prefix   |= (sh_digit << shift);
        prefmask |= (0xFFu << shift);
        rem = sh_rem;
        __syncthreads();
    }

    const unsigned thresh = prefix;
    if (threadIdx.x == 0) { cnt_gt = 0; eqcnt = 0; }
    __syncthreads();

    float* so = g_sims + (size_t)row * NT;
    int*   io = g_idx  + (size_t)row * NT;

    for (int i = threadIdx.x; i < NHW; i += blockDim.x) {
        float v = a[i];
        unsigned key = f2k(v);
        if (key > thresh) {
            int p = atomicAdd(&cnt_gt, 1);
            so[p] = v; io[p] = i;
        } else if (key == thresh) {
            int p = atomicAdd(&eqcnt, 1);
            if (p < 64) eqlist[p] = i;
        }
    }
    __syncthreads();
    if (threadIdx.x == 0) {
        int need = NT - cnt_gt;
        int m = eqcnt < 64 ? eqcnt : 64;
        for (int i = 1; i < m; i++) {
            int key = eqlist[i]; int j = i - 1;
            while (j >= 0 && eqlist[j] > key) { eqlist[j + 1] = eqlist[j]; j--; }
            eqlist[j + 1] = key;
        }
        for (int r = 0; r < need && r < m; r++) {
            int i = eqlist[r];
            so[cnt_gt + r] = a[i];
            io[cnt_gt + r] = i;
        }
    }
}

// =====================================================================
// Kernel 3: bf16-split QKV GEMM on HMMA (mma.sync.m16n8k16).
//   D[m][n] = sum_c W[m][c] * xn[n][c], 3 terms (hh + lh + hl).
//   Block 128m x 128n, 8 warps (2m x 4n), warp tile 64x32.
//   K chunks of 32; smem rows 64B data + 16B pad (conflict-free ldmatrix).
// =====================================================================
constexpr int SROW = 80;                      // smem row stride bytes
constexpr int TBUF = 128 * SROW;              // 10240 B per operand tile
__global__ void __launch_bounds__(256) tc_gemm_kernel() {
    __shared__ __align__(16) char smem_raw[4 * TBUF];   // 40 KB

    const int m0 = blockIdx.x * 128;
    const int n0 = blockIdx.y * 128;
    const int b  = blockIdx.z;
    const int tid = threadIdx.x;
    const int wrp = tid >> 5, lane = tid & 31;
    const int wm = wrp >> 2, wn = wrp & 3;    // warp grid 2(m) x 4(n)

    const uint32_t sbase = smem_u32(smem_raw);
    const uint32_t bAh = sbase, bAl = sbase + TBUF, bBh = sbase + 2 * TBUF, bBl = sbase + 3 * TBUF;

    // ldmatrix lane-address components
    const int lj = lane >> 3, lr = lane & 7;
    // A: mat0=(m0-7,k0-7) mat1=(m8-15,k0-7) mat2=(m0-7,k8-15) mat3=(m8-15,k8-15)
    const int a_row = wm * 64 + (lj & 1) * 8 + lr;
    const int a_kb  = (lj >> 1) * 16;
    // B: mat0=(n0-7,k0-7) mat1=(n0-7,k8-15) mat2=(n8-15,k0-7) mat3=(n8-15,k8-15)
    const int b_row = wn * 32 + (lj >> 1) * 8 + lr;
    const int b_kb  = (lj & 1) * 16;

    float acc[4][4][4];
#pragma unroll
    for (int i = 0; i < 4; i++)
#pragma unroll
        for (int j = 0; j < 4; j++)
#pragma unroll
            for (int r = 0; r < 4; r++) acc[i][j][r] = 0.f;

    for (int kc = 0; kc < 8; kc++) {
        const int k0 = kc * 32;
        // stage 4 operand tiles: 128 rows x 32 bf16 (64B) each
#pragma unroll
        for (int it = tid; it < 512; it += 256) {
            int row = it >> 2, c = it & 3;
            uint32_t doff = (uint32_t)(row * SROW + c * 16);
            size_t wi = ((size_t)(m0 + row) * NC + k0) >> 3;   // uint4 index
            ((uint4*)(smem_raw + 0 * TBUF + doff))[0] = ((const uint4*)g_wh)[wi + c];
            ((uint4*)(smem_raw + 1 * TBUF + doff))[0] = ((const uint4*)g_wl)[wi + c];
            size_t xi = (((size_t)b * NHW + n0 + row) * NC + k0) >> 3;
            ((uint4*)(smem_raw + 2 * TBUF + doff))[0] = ((const uint4*)g_xh)[xi + c];
            ((uint4*)(smem_raw + 3 * TBUF + doff))[0] = ((const uint4*)g_xl)[xi + c];
        }
        __syncthreads();

#pragma unroll
        for (int ks = 0; ks < 2; ks++) {
            const int kb = ks * 32;
            uint32_t ah[4][4], al[4][4], bh[2][4], bl[2][4];
#pragma unroll
            for (int mt = 0; mt < 4; mt++) {
                uint32_t ao = (uint32_t)((a_row + mt * 16) * SROW + a_kb + kb);
                ldsm4(ah[mt], bAh + ao);
                ldsm4(al[mt], bAl + ao);
            }
#pragma unroll
            for (int bt = 0; bt < 2; bt++) {
                uint32_t bo = (uint32_t)((b_row + bt * 16) * SROW + b_kb + kb);
                ldsm4(bh[bt], bBh + bo);
                ldsm4(bl[bt], bBl + bo);
            }
#pragma unroll
            for (int mt = 0; mt < 4; mt++)
#pragma unroll
                for (int bt = 0; bt < 2; bt++)
#pragma unroll
                    for (int sub = 0; sub < 2; sub++) {
                        int nt = bt * 2 + sub;
                        mma16816(acc[mt][nt], ah[mt], &bh[bt][sub * 2]);   // hh
                        mma16816(acc[mt][nt], al[mt], &bh[bt][sub * 2]);   // lh
                        mma16816(acc[mt][nt], ah[mt], &bl[bt][sub * 2]);   // hl
                    }
        }
        __syncthreads();
    }

    // epilogue: 4 chunks of 32 n; stage [n][m] in smem, then coalesced stores
    float* ep = (float*)smem_raw;            // [32][132]
    const int g = lane >> 2, q = lane & 3;
    for (int ci = 0; ci < 4; ci++) {
        if (wn == ci) {
#pragma unroll
            for (int mt = 0; mt < 4; mt++)
#pragma unroll
                for (int nt = 0; nt < 4; nt++) {
                    int nn = nt * 8 + 2 * q;
                    int m  = wm * 64 + mt * 16 + g;
                    ep[nn * 132 + m]           = acc[mt][nt][0];
                    ep[(nn + 1) * 132 + m]     = acc[mt][nt][1];
                    ep[nn * 132 + m + 8]       = acc[mt][nt][2];
                    ep[(nn + 1) * 132 + m + 8] = acc[mt][nt][3];
                }
        }
        __syncthreads();

        int nrow = tid >> 3, seg = (tid & 7) * 16;
        int n = n0 + ci * 32 + nrow;
        const float* src = ep + nrow * 132 + seg;
        float* ydst = g_yt + ((size_t)b * NHW + n) * MTOT + m0 + seg;
#pragma unroll
        for (int i = 0; i < 16; i += 4)
            *(float4*)(ydst + i) = make_float4(src[i], src[i + 1], src[i + 2], src[i + 3]);
        if (m0 >= 512) {
            float* adst = g_acc + ((size_t)b * NHW + n) * NC + (m0 - 512) + seg;
#pragma unroll
            for (int i = 0; i < 16; i += 4)
                *(float4*)(adst + i) = make_float4(src[i], src[i + 1], src[i + 2], src[i + 3]);
        }
        __syncthreads();
    }
}

// =====================================================================
// Kernel 4: attention per (s, head, b) tile (SIMT fp32, unchanged).
// =====================================================================
constexpr int KSLD = NDH + 4;

__global__ void __launch_bounds__(128) attn_kernel() {
    const int s = blockIdx.x, h = blockIdx.y, b = blockIdx.z;
    const int t = threadIdx.x;

    __shared__ float ks[NT][KSLD];
    __shared__ float vs[NT][KSLD];
    __shared__ int   idxv[NT];

    const int gi  = (b * NS + s) * NT + t;
    const int idx = g_idx[gi];
    const float sim = g_sims[gi];
    idxv[t] = idx;

    const float* yrow = g_yt + ((size_t)b * NHW + idx) * MTOT + h * NDH;
    float q[NDH];
#pragma unroll
    for (int j = 0; j < 8; j++) {
        float4 qv = *(const float4*)(yrow + j * 4);
        q[j * 4 + 0] = qv.x; q[j * 4 + 1] = qv.y; q[j * 4 + 2] = qv.z; q[j * 4 + 3] = qv.w;
        float4 kv = *(const float4*)(yrow + 256 + j * 4);
        *(float4*)&ks[t][j * 4] = kv;
        float4 vv = *(const float4*)(yrow + 512 + j * 4);
        vv.x *= sim; vv.y *= sim; vv.z *= sim; vv.w *= sim;
        *(float4*)&vs[t][j * 4] = vv;
    }
    __syncthreads();

    float mx = -1e30f, l = 0.f;
    float o[NDH];
#pragma unroll
    for (int c = 0; c < NDH; c++) o[c] = 0.f;

    for (int u0 = 0; u0 < NT; u0 += 16) {
        float sc[16];
        float cm = -1e30f;
#pragma unroll
        for (int j = 0; j < 16; j++) {
            float a = 0.f;
#pragma unroll
            for (int c = 0; c < NDH; c += 4) {
                float4 kv = *(const float4*)&ks[u0 + j][c];
                a += q[c] * kv.x + q[c + 1] * kv.y + q[c + 2] * kv.z + q[c + 3] * kv.w;
            }
            sc[j] = a * ATT_SCALE;
            cm = fmaxf(cm, sc[j]);
        }
        float mn = fmaxf(mx, cm);
        float corr = __expf(mx - mn);
        l *= corr;
#pragma unroll
        for (int c = 0; c < NDH; c++) o[c] *= corr;
#pragma unroll
        for (int j = 0; j < 16; j++) {
            float p = __expf(sc[j] - mn);
            l += p;
#pragma unroll
            for (int c = 0; c < NDH; c += 4) {
                float4 vv = *(const float4*)&vs[u0 + j][c];
                o[c + 0] += p * vv.x; o[c + 1] += p * vv.y;
                o[c + 2] += p * vv.z; o[c + 3] += p * vv.w;
            }
        }
        mx = mn;
    }

    const float wscale = sim / l;
    __syncthreads();
#pragma unroll
    for (int c = 0; c < NDH; c++) ks[t][c] = o[c] * wscale;
    __syncthreads();

    const int lane = t & 31, wrp = t >> 5;
    for (int r = 0; r < 32; r++) {
        int tt = r * 4 + wrp;
        float val = ks[tt][lane];
        atomicAdd(&g_acc[((size_t)b * NHW + idxv[tt]) * NC + h * NDH + lane], val);
    }
}

// =====================================================================
// Kernel 5: transpose accumulator (B, HW, C) -> out (B, C, HW)
// =====================================================================
__global__ void __launch_bounds__(256) transpose_kernel(float* __restrict__ out) {
    __shared__ float tile[32][33];
    const int b  = blockIdx.z;
    const int n0 = blockIdx.x * 32;
    const int c0 = blockIdx.y * 32;
    const int tx = threadIdx.x, ty = threadIdx.y;
#pragma unroll
    for (int j = 0; j < 32; j += 8)
        tile[ty + j][tx] = g_acc[((size_t)b * NHW + n0 + ty + j) * NC + c0 + tx];
    __syncthreads();
#pragma unroll
    for (int j = 0; j < 32; j += 8)
        out[((size_t)b * NC + c0 + ty + j) * NHW + n0 + tx] = tile[tx][ty + j];
}

// =====================================================================
extern "C" void kernel_launch(void* const* d_in, const int* in_sizes, int n_in,
                              void* d_out, int out_size) {
    const float* x    = (const float*)d_in[0];
    const float* aff  = (const float*)d_in[1];
    const float* lnw  = (const float*)d_in[2];
    const float* lnb  = (const float*)d_in[3];
    const float* wq   = (const float*)d_in[4];
    const float* wk   = (const float*)d_in[5];
    const float* wv   = (const float*)d_in[6];
    float* out = (float*)d_out;

    ln_stats_kernel<<<(NB * NHW) / 256, 256>>>(x);
    xsplit_kernel<<<dim3(NHW / 32, NC / 32, NB), dim3(32, 8)>>>(x, lnw, lnb);
    wsplit_kernel<<<MTOT, 256>>>(wq, wk, wv);
    topk_kernel<<<NB * NS, 256>>>(aff);
    tc_gemm_kernel<<<dim3(MTOT / 128, NHW / 128, NB), 256>>>();
    attn_kernel<<<dim3(NS, NHEADS, NB), 128>>>();
    transpose_kernel<<<dim3(NHW / 32, NC / 32, NB), dim3(32, 8)>>>(out);
}

// round 6
// speedup vs baseline: 1.6705x; 1.6705x over previous
#include <cuda_runtime.h>
#include <cuda_bf16.h>
#include <cstdint>
#include <math.h>

// ---------------- problem constants ----------------
constexpr int NB     = 2;
constexpr int NC     = 256;     // channels (= QK)
constexpr int NHW    = 16384;   // H*W
constexpr int NS     = 256;     // superpixels
constexpr int NT     = 128;     // top-k
constexpr int NHEADS = 8;
constexpr int NDH    = 32;      // head dim
constexpr int MTOT   = 768;     // q(256) + k(256) + v(256)
constexpr float EPSV      = 1e-5f;
constexpr float ATT_SCALE = 0.17677669529663687f;  // 1/sqrt(32)

// ---------------- scratch (device globals; no allocations allowed) ----------
__device__ float  g_yt [(size_t)NB * NHW * MTOT];        // qkv, n-major fp32
__device__ float  g_acc[(size_t)NB * NHW * NC];          // output accumulator (n-major)
__device__ float  g_sims[NB * NS * NT];
__device__ int    g_idx [NB * NS * NT];
__device__ float2 g_stat[NB * NHW];                      // (mu, inv) per pixel
__device__ __nv_bfloat16 g_xh[(size_t)NB * NHW * NC];    // ln(x) hi, [b][n][c]
__device__ __nv_bfloat16 g_xl[(size_t)NB * NHW * NC];    // ln(x) lo
__device__ __nv_bfloat16 g_wh[MTOT * NC];                // stacked W hi
__device__ __nv_bfloat16 g_wl[MTOT * NC];                // stacked W lo

// ---------------- PTX helpers (baseline ISA only, valid on compute_103) ----
__device__ __forceinline__ uint32_t smem_u32(const void* p) {
    uint32_t a;
    asm("{ .reg .u64 t; cvta.to.shared.u64 t, %1; cvt.u32.u64 %0, t; }" : "=r"(a) : "l"(p));
    return a;
}
__device__ __forceinline__ void ldsm4(uint32_t* r, uint32_t addr) {
    asm volatile("ldmatrix.sync.aligned.m8n8.x4.shared.b16 {%0,%1,%2,%3}, [%4];"
                 : "=r"(r[0]), "=r"(r[1]), "=r"(r[2]), "=r"(r[3]) : "r"(addr));
}
__device__ __forceinline__ void mma16816(float* d, const uint32_t* a, const uint32_t* b) {
    asm volatile("mma.sync.aligned.m16n8k16.row.col.f32.bf16.bf16.f32 "
                 "{%0,%1,%2,%3}, {%4,%5,%6,%7}, {%8,%9}, {%0,%1,%2,%3};"
                 : "+f"(d[0]), "+f"(d[1]), "+f"(d[2]), "+f"(d[3])
                 : "r"(a[0]), "r"(a[1]), "r"(a[2]), "r"(a[3]), "r"(b[0]), "r"(b[1]));
}
__device__ __forceinline__ void cp16(uint32_t dst, const void* src) {
    asm volatile("{ .reg .u64 g; cvta.to.global.u64 g, %1; cp.async.ca.shared.global [%0], [g], 16; }"
                 :: "r"(dst), "l"(src) : "memory");
}
#define CP_COMMIT() asm volatile("cp.async.commit_group;" ::: "memory")
template <int N>
__device__ __forceinline__ void cp_wait() {
    asm volatile("cp.async.wait_group %0;" :: "n"(N) : "memory");
}

// =====================================================================
// Kernel 1a: LayerNorm statistics per pixel (coalesced over n).
// =====================================================================
__global__ void __launch_bounds__(256) ln_stats_kernel(const float* __restrict__ x) {
    int p = blockIdx.x * blockDim.x + threadIdx.x;
    int b = p / NHW;
    int n = p - b * NHW;
    const float* xb = x + (size_t)b * NC * NHW + n;
    float s = 0.f, ss = 0.f;
#pragma unroll 8
    for (int c = 0; c < NC; c++) {
        float v = xb[(size_t)c * NHW];
        s += v; ss += v * v;
    }
    float mu  = s * (1.0f / NC);
    float var = ss * (1.0f / NC) - mu * mu;
    g_stat[p] = make_float2(mu, rsqrtf(var + EPSV));
}

// =====================================================================
// Kernel 1b: normalize + transpose to [b][n][c] + bf16 hi/lo split.
// =====================================================================
__global__ void __launch_bounds__(256) xsplit_kernel(const float* __restrict__ x,
                                                     const float* __restrict__ lw,
                                                     const float* __restrict__ lb) {
    __shared__ float tile[32][33];
    const int b  = blockIdx.z;
    const int n0 = blockIdx.x * 32;
    const int c0 = blockIdx.y * 32;
    const int tx = threadIdx.x, ty = threadIdx.y;
#pragma unroll
    for (int j = 0; j < 32; j += 8)
        tile[ty + j][tx] = x[((size_t)b * NC + c0 + ty + j) * NHW + n0 + tx];
    __syncthreads();
    const float w = lw[c0 + tx], bi = lb[c0 + tx];
#pragma unroll
    for (int j = 0; j < 32; j += 8) {
        int n = n0 + ty + j;
        float2 st = g_stat[b * NHW + n];
        float v = (tile[tx][ty + j] - st.x) * st.y * w + bi;
        __nv_bfloat16 hi = __float2bfloat16_rn(v);
        __nv_bfloat16 lo = __float2bfloat16_rn(v - __bfloat162float(hi));
        size_t o = ((size_t)b * NHW + n) * NC + c0 + tx;
        g_xh[o] = hi;
        g_xl[o] = lo;
    }
}

// =====================================================================
// Kernel 1c: split stacked W (wq;wk;wv) into bf16 hi/lo.
// =====================================================================
__global__ void __launch_bounds__(256) wsplit_kernel(const float* __restrict__ wq,
                                                     const float* __restrict__ wk,
                                                     const float* __restrict__ wv) {
    int m = blockIdx.x, c = threadIdx.x;
    const float* src = (m < 256) ? (wq + (size_t)m * NC)
                     : (m < 512) ? (wk + (size_t)(m - 256) * NC)
                                 : (wv + (size_t)(m - 512) * NC);
    float v = src[c];
    __nv_bfloat16 hi = __float2bfloat16_rn(v);
    __nv_bfloat16 lo = __float2bfloat16_rn(v - __bfloat162float(hi));
    g_wh[(size_t)m * NC + c] = hi;
    g_wl[(size_t)m * NC + c] = lo;
}

// =====================================================================
// Kernel 2: exact top-128 per row. Pass 1: warp-aggregated byte histogram.
// Elements with top byte > pivot are emitted directly; pivot-byte candidates
// (~370 expected) compacted to smem and refined with 3 tiny radix passes.
// Fallback to full-gmem passes if candidates overflow.
// =====================================================================
__device__ __forceinline__ unsigned f2k(float f) {
    unsigned u = __float_as_uint(f);
    return (u & 0x80000000u) ? ~u : (u | 0x80000000u);
}
constexpr int TCAP = 4096;

__global__ void __launch_bounds__(512) topk_kernel(const float* __restrict__ aff) {
    const int row = blockIdx.x;
    const float* a = aff + (size_t)row * NHW;
    const int tid = threadIdx.x, lane = tid & 31;

    __shared__ unsigned hist[256];
    __shared__ float candV[TCAP];
    __shared__ int   candI[TCAP];
    __shared__ unsigned sh_digit, sh_rem;
    __shared__ int cnt, nc, eqcnt;
    __shared__ int eqlist[64];

    for (int i = tid; i < 256; i += 512) hist[i] = 0;
    if (tid == 0) { cnt = 0; nc = 0; eqcnt = 0; }
    __syncthreads();

    // ---- pass 1: top-byte histogram, warp-aggregated ----
    for (int i = tid; i < NHW; i += 512) {
        unsigned byte = f2k(a[i]) >> 24;
        unsigned m = __match_any_sync(0xFFFFFFFFu, byte);
        if ((int)(__ffs(m) - 1) == lane) atomicAdd(&hist[byte], __popc(m));
    }
    __syncthreads();
    if (tid == 0) {
        unsigned r = NT;
        int d = 255;
        for (; d > 0; d--) {
            unsigned c = hist[d];
            if (c >= r) break;
            r -= c;
        }
        sh_digit = (unsigned)d;
        sh_rem = r;
    }
    __syncthreads();
    const unsigned dtop = sh_digit;
    unsigned rem = sh_rem;

    float* so = g_sims + (size_t)row * NT;
    int*   io = g_idx  + (size_t)row * NT;

    // ---- sweep: direct-emit (> pivot byte), compact candidates (== pivot) ----
    for (int i = tid; i < NHW; i += 512) {
        float v = a[i];
        unsigned byte = f2k(v) >> 24;
        if (byte > dtop) {
            int p = atomicAdd(&cnt, 1);
            so[p] = v; io[p] = i;
        } else if (byte == dtop) {
            int q = atomicAdd(&nc, 1);
            if (q < TCAP) { candV[q] = v; candI[q] = i; }
        }
    }
    __syncthreads();

    unsigned prefix  = dtop << 24;
    unsigned prefmask = 0xFF000000u;
    const bool incache = (nc <= TCAP);
    const int ncand = incache ? nc : 0;

    // ---- 3 more radix passes (smem candidates, or gmem fallback) ----
    for (int shift = 16; shift >= 0; shift -= 8) {
        for (int i = tid; i < 256; i += 512) hist[i] = 0;
        __syncthreads();
        if (incache) {
            for (int j = tid; j < ncand; j += 512) {
                unsigned key = f2k(candV[j]);
                if ((key & prefmask) == prefix) {
                    unsigned byte = (key >> shift) & 255u;
                    unsigned m = __match_any_sync(__activemask(), byte);
                    if ((int)(__ffs(m) - 1) == lane) atomicAdd(&hist[byte], __popc(m));
                }
            }
        } else {
            for (int i = tid; i < NHW; i += 512) {
                unsigned key = f2k(a[i]);
                if ((key & prefmask) == prefix) {
                    unsigned byte = (key >> shift) & 255u;
                    unsigned m = __match_any_sync(__activemask(), byte);
                    if ((int)(__ffs(m) - 1) == lane) atomicAdd(&hist[byte], __popc(m));
                }
            }
        }
        __syncthreads();
        if (tid == 0) {
            unsigned r = rem;
            int d = 255;
            for (; d > 0; d--) {
                unsigned c = hist[d];
                if (c >= r) break;
                r -= c;
            }
            sh_digit = (unsigned)d;
            sh_rem = r;
        }
        __syncthreads();
        prefix   |= (sh_digit << shift);
        prefmask |= (0xFFu << shift);
        rem = sh_rem;
        __syncthreads();
    }

    // ---- final emit among candidates ----
    const unsigned thresh = prefix;
    if (incache) {
        for (int j = tid; j < ncand; j += 512) {
            unsigned key = f2k(candV[j]);
            if (key > thresh) {
                int p = atomicAdd(&cnt, 1);
                so[p] = candV[j]; io[p] = candI[j];
            } else if (key == thresh) {
                int p = atomicAdd(&eqcnt, 1);
                if (p < 64) eqlist[p] = candI[j];
            }
        }
    } else {
        for (int i = tid; i < NHW; i += 512) {
            float v = a[i];
            unsigned key = f2k(v);
            if (key > thresh && (key >> 24) == dtop) {
                int p = atomicAdd(&cnt, 1);
                so[p] = v; io[p] = i;
            } else if (key == thresh) {
                int p = atomicAdd(&eqcnt, 1);
                if (p < 64) eqlist[p] = i;
            }
        }
    }
    __syncthreads();
    if (tid == 0) {
        int need = NT - cnt;
        int m = eqcnt < 64 ? eqcnt : 64;
        for (int i = 1; i < m; i++) {
            int key = eqlist[i]; int j = i - 1;
            while (j >= 0 && eqlist[j] > key) { eqlist[j + 1] = eqlist[j]; j--; }
            eqlist[j + 1] = key;
        }
        float tv = __uint_as_float((thresh & 0x80000000u) ? (thresh & 0x7FFFFFFFu) : ~thresh);
        for (int r = 0; r < need && r < m; r++) {
            so[cnt + r] = tv;
            io[cnt + r] = eqlist[r];
        }
    }
}

// =====================================================================
// Kernel 3: bf16-split QKV GEMM on HMMA, cp.async double-buffered.
//   Block 128m x 128n, 8 warps (2m x 4n), K chunks of 32, 2 smem stages.
//   Tiles: 128 rows x 64B, XOR swizzle chunk^= (row>>1)&3 (conflict-free
//   for both cp.async writes and ldmatrix reads).
// =====================================================================
constexpr int TILEB = 8192;          // one operand tile: 128 * 64 B
constexpr int STAGEB = 4 * TILEB;    // Ah, Al, Bh, Bl
__global__ void __launch_bounds__(256) tc_gemm_kernel() {
    extern __shared__ __align__(128) char smem_raw[];   // 2 * 32 KB

    const int m0 = blockIdx.x * 128;
    const int n0 = blockIdx.y * 128;
    const int b  = blockIdx.z;
    const int tid = threadIdx.x;
    const int wrp = tid >> 5, lane = tid & 31;
    const int wm = wrp >> 2, wn = wrp & 3;    // warp grid 2(m) x 4(n)

    const uint32_t sbase = smem_u32(smem_raw);
    const size_t xbase = (size_t)b * NHW * NC;

    // ldmatrix lane-address components
    const int lj = lane >> 3, lr = lane & 7;
    const int a_row = wm * 64 + (lj & 1) * 8 + lr;   // + mt*16
    const int a_j0  = lj >> 1;                        // + ks*2
    const int b_row = wn * 32 + (lj >> 1) * 8 + lr;  // + bt*16
    const int b_j0  = lj & 1;                         // + ks*2

    float acc[4][4][4];
#pragma unroll
    for (int i = 0; i < 4; i++)
#pragma unroll
        for (int j = 0; j < 4; j++)
#pragma unroll
            for (int r = 0; r < 4; r++) acc[i][j][r] = 0.f;

    // ---- stage loader: 2048 16B chunks over 256 threads ----
    auto load_stage = [&](int stage, int k0) {
        const uint32_t sb = sbase + stage * STAGEB;
#pragma unroll
        for (int i = 0; i < 8; i++) {
            const int arr = i >> 1;
            const int rem = ((i & 1) << 8) + tid;
            const int r = rem >> 2, c = rem & 3;
            uint32_t dst = sb + arr * TILEB + r * 64 + ((c ^ ((r >> 1) & 3)) << 4);
            const __nv_bfloat16* src;
            if (arr == 0)      src = g_wh + (size_t)(m0 + r) * NC + k0;
            else if (arr == 1) src = g_wl + (size_t)(m0 + r) * NC + k0;
            else if (arr == 2) src = g_xh + xbase + (size_t)(n0 + r) * NC + k0;
            else               src = g_xl + xbase + (size_t)(n0 + r) * NC + k0;
            cp16(dst, src + c * 8);
        }
        CP_COMMIT();
    };

    load_stage(0, 0);

    for (int kc = 0; kc < 8; kc++) {
        if (kc < 7) load_stage((kc + 1) & 1, (kc + 1) * 32);
        if (kc < 7) cp_wait<1>(); else cp_wait<0>();
        __syncthreads();

        const uint32_t sb = sbase + (kc & 1) * STAGEB;
        const uint32_t bAh = sb, bAl = sb + TILEB, bBh = sb + 2 * TILEB, bBl = sb + 3 * TILEB;

#pragma unroll
        for (int ks = 0; ks < 2; ks++) {
            uint32_t bh[2][4], bl[2][4];
#pragma unroll
            for (int bt = 0; bt < 2; bt++) {
                int r = b_row + bt * 16;
                int j = b_j0 + ks * 2;
                uint32_t off = (uint32_t)(r * 64 + ((j ^ ((r >> 1) & 3)) << 4));
                ldsm4(bh[bt], bBh + off);
                ldsm4(bl[bt], bBl + off);
            }
#pragma unroll
            for (int mt = 0; mt < 4; mt++) {
                int r = a_row + mt * 16;
                int j = a_j0 + ks * 2;
                uint32_t off = (uint32_t)(r * 64 + ((j ^ ((r >> 1) & 3)) << 4));
                uint32_t ah[4], al[4];
                ldsm4(ah, bAh + off);
                ldsm4(al, bAl + off);
#pragma unroll
                for (int bt = 0; bt < 2; bt++)
#pragma unroll
                    for (int sub = 0; sub < 2; sub++) {
                        int nt = bt * 2 + sub;
                        mma16816(acc[mt][nt], ah, &bh[bt][sub * 2]);   // hh
                        mma16816(acc[mt][nt], al, &bh[bt][sub * 2]);   // lh
                        mma16816(acc[mt][nt], ah, &bl[bt][sub * 2]);   // hl
                    }
            }
        }
        __syncthreads();
    }

    // ---- epilogue: 4 chunks of 32 n; stage [n][m] in smem, coalesced stores
    float* ep = (float*)smem_raw;            // [32][132]
    const int g = lane >> 2, q = lane & 3;
    for (int ci = 0; ci < 4; ci++) {
        if (wn == ci) {
#pragma unroll
            for (int mt = 0; mt < 4; mt++)
#pragma unroll
                for (int nt = 0; nt < 4; nt++) {
                    int nn = nt * 8 + 2 * q;
                    int m  = wm * 64 + mt * 16 + g;
                    ep[nn * 132 + m]           = acc[mt][nt][0];
                    ep[(nn + 1) * 132 + m]     = acc[mt][nt][1];
                    ep[nn * 132 + m + 8]       = acc[mt][nt][2];
                    ep[(nn + 1) * 132 + m + 8] = acc[mt][nt][3];
                }
        }
        __syncthreads();

        int nrow = tid >> 3, seg = (tid & 7) * 16;
        int n = n0 + ci * 32 + nrow;
        const float* src = ep + nrow * 132 + seg;
        float* ydst = g_yt + ((size_t)b * NHW + n) * MTOT + m0 + seg;
#pragma unroll
        for (int i = 0; i < 16; i += 4)
            *(float4*)(ydst + i) = make_float4(src[i], src[i + 1], src[i + 2], src[i + 3]);
        if (m0 >= 512) {
            float* adst = g_acc + ((size_t)b * NHW + n) * NC + (m0 - 512) + seg;
#pragma unroll
            for (int i = 0; i < 16; i += 4)
                *(float4*)(adst + i) = make_float4(src[i], src[i + 1], src[i + 2], src[i + 3]);
        }
        __syncthreads();
    }
}

// =====================================================================
// Kernel 4: attention per (s, head, b) tile (SIMT fp32, unchanged).
// =====================================================================
constexpr int KSLD = NDH + 4;

__global__ void __launch_bounds__(128) attn_kernel() {
    const int s = blockIdx.x, h = blockIdx.y, b = blockIdx.z;
    const int t = threadIdx.x;

    __shared__ float ks[NT][KSLD];
    __shared__ float vs[NT][KSLD];
    __shared__ int   idxv[NT];

    const int gi  = (b * NS + s) * NT + t;
    const int idx = g_idx[gi];
    const float sim = g_sims[gi];
    idxv[t] = idx;

    const float* yrow = g_yt + ((size_t)b * NHW + idx) * MTOT + h * NDH;
    float q[NDH];
#pragma unroll
    for (int j = 0; j < 8; j++) {
        float4 qv = *(const float4*)(yrow + j * 4);
        q[j * 4 + 0] = qv.x; q[j * 4 + 1] = qv.y; q[j * 4 + 2] = qv.z; q[j * 4 + 3] = qv.w;
        float4 kv = *(const float4*)(yrow + 256 + j * 4);
        *(float4*)&ks[t][j * 4] = kv;
        float4 vv = *(const float4*)(yrow + 512 + j * 4);
        vv.x *= sim; vv.y *= sim; vv.z *= sim; vv.w *= sim;
        *(float4*)&vs[t][j * 4] = vv;
    }
    __syncthreads();

    float mx = -1e30f, l = 0.f;
    float o[NDH];
#pragma unroll
    for (int c = 0; c < NDH; c++) o[c] = 0.f;

    for (int u0 = 0; u0 < NT; u0 += 16) {
        float sc[16];
        float cm = -1e30f;
#pragma unroll
        for (int j = 0; j < 16; j++) {
            float a = 0.f;
#pragma unroll
            for (int c = 0; c < NDH; c += 4) {
                float4 kv = *(const float4*)&ks[u0 + j][c];
                a += q[c] * kv.x + q[c + 1] * kv.y + q[c + 2] * kv.z + q[c + 3] * kv.w;
            }
            sc[j] = a * ATT_SCALE;
            cm = fmaxf(cm, sc[j]);
        }
        float mn = fmaxf(mx, cm);
        float corr = __expf(mx - mn);
        l *= corr;
#pragma unroll
        for (int c = 0; c < NDH; c++) o[c] *= corr;
#pragma unroll
        for (int j = 0; j < 16; j++) {
            float p = __expf(sc[j] - mn);
            l += p;
#pragma unroll
            for (int c = 0; c < NDH; c += 4) {
                float4 vv = *(const float4*)&vs[u0 + j][c];
                o[c + 0] += p * vv.x; o[c + 1] += p * vv.y;
                o[c + 2] += p * vv.z; o[c + 3] += p * vv.w;
            }
        }
        mx = mn;
    }

    const float wscale = sim / l;
    __syncthreads();
#pragma unroll
    for (int c = 0; c < NDH; c++) ks[t][c] = o[c] * wscale;
    __syncthreads();

    const int lane = t & 31, wrp = t >> 5;
    for (int r = 0; r < 32; r++) {
        int tt = r * 4 + wrp;
        float val = ks[tt][lane];
        atomicAdd(&g_acc[((size_t)b * NHW + idxv[tt]) * NC + h * NDH + lane], val);
    }
}

// =====================================================================
// Kernel 5: transpose accumulator (B, HW, C) -> out (B, C, HW)
// =====================================================================
__global__ void __launch_bounds__(256) transpose_kernel(float* __restrict__ out) {
    __shared__ float tile[32][33];
    const int b  = blockIdx.z;
    const int n0 = blockIdx.x * 32;
    const int c0 = blockIdx.y * 32;
    const int tx = threadIdx.x, ty = threadIdx.y;
#pragma unroll
    for (int j = 0; j < 32; j += 8)
        tile[ty + j][tx] = g_acc[((size_t)b * NHW + n0 + ty + j) * NC + c0 + tx];
    __syncthreads();
#pragma unroll
    for (int j = 0; j < 32; j += 8)
        out[((size_t)b * NC + c0 + ty + j) * NHW + n0 + tx] = tile[tx][ty + j];
}

// =====================================================================
extern "C" void kernel_launch(void* const* d_in, const int* in_sizes, int n_in,
                              void* d_out, int out_size) {
    const float* x    = (const float*)d_in[0];
    const float* aff  = (const float*)d_in[1];
    const float* lnw  = (const float*)d_in[2];
    const float* lnb  = (const float*)d_in[3];
    const float* wq   = (const float*)d_in[4];
    const float* wk   = (const float*)d_in[5];
    const float* wv   = (const float*)d_in[6];
    float* out = (float*)d_out;

    cudaFuncSetAttribute(tc_gemm_kernel,
                         cudaFuncAttributeMaxDynamicSharedMemorySize, 2 * STAGEB);

    ln_stats_kernel<<<(NB * NHW) / 256, 256>>>(x);
    xsplit_kernel<<<dim3(NHW / 32, NC / 32, NB), dim3(32, 8)>>>(x, lnw, lnb);
    wsplit_kernel<<<MTOT, 256>>>(wq, wk, wv);
    topk_kernel<<<NB * NS, 512>>>(aff);
    tc_gemm_kernel<<<dim3(MTOT / 128, NHW / 128, NB), 256, 2 * STAGEB>>>();
    attn_kernel<<<dim3(NS, NHEADS, NB), 128>>>();
    transpose_kernel<<<dim3(NHW / 32, NC / 32, NB), dim3(32, 8)>>>(out);
}

// round 8
// speedup vs baseline: 1.7626x; 1.0551x over previous
#include <cuda_runtime.h>
#include <cuda_bf16.h>
#include <cstdint>
#include <math.h>

// ---------------- problem constants ----------------
constexpr int NB     = 2;
constexpr int NC     = 256;     // channels (= QK)
constexpr int NHW    = 16384;   // H*W
constexpr int NS     = 256;     // superpixels
constexpr int NT     = 128;     // top-k
constexpr int NHEADS = 8;
constexpr int NDH    = 32;      // head dim
constexpr int MTOT   = 768;     // q(256) + k(256) + v(256)
constexpr float EPSV      = 1e-5f;
constexpr float ATT_SCALE = 0.17677669529663687f;  // 1/sqrt(32)

// ---------------- scratch (device globals; no allocations allowed) ----------
__device__ float  g_yt [(size_t)NB * NHW * MTOT];        // qkv, n-major fp32
__device__ float  g_acc[(size_t)NB * NHW * NC];          // output accumulator (n-major)
__device__ float  g_sims[NB * NS * NT];
__device__ int    g_idx [NB * NS * NT];
__device__ float2 g_stat[NB * NHW];                      // (mu, inv) per pixel
__device__ __nv_bfloat16 g_xh[(size_t)NB * NHW * NC];    // ln(x) hi, [b][n][c]
__device__ __nv_bfloat16 g_xl[(size_t)NB * NHW * NC];    // ln(x) lo
__device__ __nv_bfloat16 g_wh[MTOT * NC];                // stacked W hi
__device__ __nv_bfloat16 g_wl[MTOT * NC];                // stacked W lo

// ---------------- PTX helpers (baseline ISA only, valid on compute_103) ----
__device__ __forceinline__ uint32_t smem_u32(const void* p) {
    uint32_t a;
    asm("{ .reg .u64 t; cvta.to.shared.u64 t, %1; cvt.u32.u64 %0, t; }" : "=r"(a) : "l"(p));
    return a;
}
__device__ __forceinline__ void ldsm4(uint32_t* r, uint32_t addr) {
    asm volatile("ldmatrix.sync.aligned.m8n8.x4.shared.b16 {%0,%1,%2,%3}, [%4];"
                 : "=r"(r[0]), "=r"(r[1]), "=r"(r[2]), "=r"(r[3]) : "r"(addr));
}
__device__ __forceinline__ void ldsm4t(uint32_t* r, uint32_t addr) {
    asm volatile("ldmatrix.sync.aligned.m8n8.x4.trans.shared.b16 {%0,%1,%2,%3}, [%4];"
                 : "=r"(r[0]), "=r"(r[1]), "=r"(r[2]), "=r"(r[3]) : "r"(addr));
}
__device__ __forceinline__ void mma16816(float* d, const uint32_t* a, const uint32_t* b) {
    asm volatile("mma.sync.aligned.m16n8k16.row.col.f32.bf16.bf16.f32 "
                 "{%0,%1,%2,%3}, {%4,%5,%6,%7}, {%8,%9}, {%0,%1,%2,%3};"
                 : "+f"(d[0]), "+f"(d[1]), "+f"(d[2]), "+f"(d[3])
                 : "r"(a[0]), "r"(a[1]), "r"(a[2]), "r"(a[3]), "r"(b[0]), "r"(b[1]));
}
__device__ __forceinline__ void mma16816b(float* d, const uint32_t* a, uint32_t b0, uint32_t b1) {
    asm volatile("mma.sync.aligned.m16n8k16.row.col.f32.bf16.bf16.f32 "
                 "{%0,%1,%2,%3}, {%4,%5,%6,%7}, {%8,%9}, {%0,%1,%2,%3};"
                 : "+f"(d[0]), "+f"(d[1]), "+f"(d[2]), "+f"(d[3])
                 : "r"(a[0]), "r"(a[1]), "r"(a[2]), "r"(a[3]), "r"(b0), "r"(b1));
}
__device__ __forceinline__ void cp16(uint32_t dst, const void* src) {
    asm volatile("{ .reg .u64 g; cvta.to.global.u64 g, %1; cp.async.ca.shared.global [%0], [g], 16; }"
                 :: "r"(dst), "l"(src) : "memory");
}
#define CP_COMMIT() asm volatile("cp.async.commit_group;" ::: "memory")
template <int N>
__device__ __forceinline__ void cp_wait() {
    asm volatile("cp.async.wait_group %0;" :: "n"(N) : "memory");
}
// pack two floats into bf16x2 hi parts + bf16x2 residual parts
__device__ __forceinline__ void hilo2(float a, float b, uint32_t& hi, uint32_t& lo) {
    __nv_bfloat16 ah = __float2bfloat16_rn(a), bh = __float2bfloat16_rn(b);
    __nv_bfloat162 hp; hp.x = ah; hp.y = bh;
    __nv_bfloat162 lp;
    lp.x = __float2bfloat16_rn(a - __bfloat162float(ah));
    lp.y = __float2bfloat16_rn(b - __bfloat162float(bh));
    hi = *(uint32_t*)&hp;
    lo = *(uint32_t*)&lp;
}

// =====================================================================
// Kernel 1a: LayerNorm statistics per pixel (coalesced over n).
// =====================================================================
__global__ void __launch_bounds__(256) ln_stats_kernel(const float* __restrict__ x) {
    int p = blockIdx.x * blockDim.x + threadIdx.x;
    int b = p / NHW;
    int n = p - b * NHW;
    const float* xb = x + (size_t)b * NC * NHW + n;
    float s = 0.f, ss = 0.f;
#pragma unroll 8
    for (int c = 0; c < NC; c++) {
        float v = xb[(size_t)c * NHW];
        s += v; ss += v * v;
    }
    float mu  = s * (1.0f / NC);
    float var = ss * (1.0f / NC) - mu * mu;
    g_stat[p] = make_float2(mu, rsqrtf(var + EPSV));
}

// =====================================================================
// Kernel 1b: normalize + transpose to [b][n][c] + bf16 hi/lo split.
// =====================================================================
__global__ void __launch_bounds__(256) xsplit_kernel(const float* __restrict__ x,
                                                     const float* __restrict__ lw,
                                                     const float* __restrict__ lb) {
    __shared__ float tile[32][33];
    const int b  = blockIdx.z;
    const int n0 = blockIdx.x * 32;
    const int c0 = blockIdx.y * 32;
    const int tx = threadIdx.x, ty = threadIdx.y;
#pragma unroll
    for (int j = 0; j < 32; j += 8)
        tile[ty + j][tx] = x[((size_t)b * NC + c0 + ty + j) * NHW + n0 + tx];
    __syncthreads();
    const float w = lw[c0 + tx], bi = lb[c0 + tx];
#pragma unroll
    for (int j = 0; j < 32; j += 8) {
        int n = n0 + ty + j;
        float2 st = g_stat[b * NHW + n];
        float v = (tile[tx][ty + j] - st.x) * st.y * w + bi;
        __nv_bfloat16 hi = __float2bfloat16_rn(v);
        __nv_bfloat16 lo = __float2bfloat16_rn(v - __bfloat162float(hi));
        size_t o = ((size_t)b * NHW + n) * NC + c0 + tx;
        g_xh[o] = hi;
        g_xl[o] = lo;
    }
}

// =====================================================================
// Kernel 1c: split stacked W (wq;wk;wv) into bf16 hi/lo.
// =====================================================================
__global__ void __launch_bounds__(256) wsplit_kernel(const float* __restrict__ wq,
                                                     const float* __restrict__ wk,
                                                     const float* __restrict__ wv) {
    int m = blockIdx.x, c = threadIdx.x;
    const float* src = (m < 256) ? (wq + (size_t)m * NC)
                     : (m < 512) ? (wk + (size_t)(m - 256) * NC)
                                 : (wv + (size_t)(m - 512) * NC);
    float v = src[c];
    __nv_bfloat16 hi = __float2bfloat16_rn(v);
    __nv_bfloat16 lo = __float2bfloat16_rn(v - __bfloat162float(hi));
    g_wh[(size_t)m * NC + c] = hi;
    g_wl[(size_t)m * NC + c] = lo;
}

// =====================================================================
// Kernel 2: exact top-128 per row (warp-aggregated radix select).
// =====================================================================
__device__ __forceinline__ unsigned f2k(float f) {
    unsigned u = __float_as_uint(f);
    return (u & 0x80000000u) ? ~u : (u | 0x80000000u);
}
constexpr int TCAP = 4096;

__global__ void __launch_bounds__(512) topk_kernel(const float* __restrict__ aff) {
    const int row = blockIdx.x;
    const float* a = aff + (size_t)row * NHW;
    const int tid = threadIdx.x, lane = tid & 31;

    __shared__ unsigned hist[256];
    __shared__ float candV[TCAP];
    __shared__ int   candI[TCAP];
    __shared__ unsigned sh_digit, sh_rem;
    __shared__ int cnt, nc, eqcnt;
    __shared__ int eqlist[64];

    for (int i = tid; i < 256; i += 512) hist[i] = 0;
    if (tid == 0) { cnt = 0; nc = 0; eqcnt = 0; }
    __syncthreads();

    for (int i = tid; i < NHW; i += 512) {
        unsigned byte = f2k(a[i]) >> 24;
        unsigned m = __match_any_sync(0xFFFFFFFFu, byte);
        if ((int)(__ffs(m) - 1) == lane) atomicAdd(&hist[byte], __popc(m));
    }
    __syncthreads();
    if (tid == 0) {
        unsigned r = NT;
        int d = 255;
        for (; d > 0; d--) {
            unsigned c = hist[d];
            if (c >= r) break;
            r -= c;
        }
        sh_digit = (unsigned)d;
        sh_rem = r;
    }
    __syncthreads();
    const unsigned dtop = sh_digit;
    unsigned rem = sh_rem;

    float* so = g_sims + (size_t)row * NT;
    int*   io = g_idx  + (size_t)row * NT;

    for (int i = tid; i < NHW; i += 512) {
        float v = a[i];
        unsigned byte = f2k(v) >> 24;
        if (byte > dtop) {
            int p = atomicAdd(&cnt, 1);
            so[p] = v; io[p] = i;
        } else if (byte == dtop) {
            int q = atomicAdd(&nc, 1);
            if (q < TCAP) { candV[q] = v; candI[q] = i; }
        }
    }
    __syncthreads();

    unsigned prefix  = dtop << 24;
    unsigned prefmask = 0xFF000000u;
    const bool incache = (nc <= TCAP);
    const int ncand = incache ? nc : 0;

    for (int shift = 16; shift >= 0; shift -= 8) {
        for (int i = tid; i < 256; i += 512) hist[i] = 0;
        __syncthreads();
        if (incache) {
            for (int j = tid; j < ncand; j += 512) {
                unsigned key = f2k(candV[j]);
                if ((key & prefmask) == prefix) {
                    unsigned byte = (key >> shift) & 255u;
                    unsigned m = __match_any_sync(__activemask(), byte);
                    if ((int)(__ffs(m) - 1) == lane) atomicAdd(&hist[byte], __popc(m));
                }
            }
        } else {
            for (int i = tid; i < NHW; i += 512) {
                unsigned key = f2k(a[i]);
                if ((key & prefmask) == prefix) {
                    unsigned byte = (key >> shift) & 255u;
                    unsigned m = __match_any_sync(__activemask(), byte);
                    if ((int)(__ffs(m) - 1) == lane) atomicAdd(&hist[byte], __popc(m));
                }
            }
        }
        __syncthreads();
        if (tid == 0) {
            unsigned r = rem;
            int d = 255;
            for (; d > 0; d--) {
                unsigned c = hist[d];
                if (c >= r) break;
                r -= c;
            }
            sh_digit = (unsigned)d;
            sh_rem = r;
        }
        __syncthreads();
        prefix   |= (sh_digit << shift);
        prefmask |= (0xFFu << shift);
        rem = sh_rem;
        __syncthreads();
    }

    const unsigned thresh = prefix;
    if (incache) {
        for (int j = tid; j < ncand; j += 512) {
            unsigned key = f2k(candV[j]);
            if (key > thresh) {
                int p = atomicAdd(&cnt, 1);
                so[p] = candV[j]; io[p] = candI[j];
            } else if (key == thresh) {
                int p = atomicAdd(&eqcnt, 1);
                if (p < 64) eqlist[p] = candI[j];
            }
        }
    } else {
        for (int i = tid; i < NHW; i += 512) {
            float v = a[i];
            unsigned key = f2k(v);
            if (key > thresh && (key >> 24) == dtop) {
                int p = atomicAdd(&cnt, 1);
                so[p] = v; io[p] = i;
            } else if (key == thresh) {
                int p = atomicAdd(&eqcnt, 1);
                if (p < 64) eqlist[p] = i;
            }
        }
    }
    __syncthreads();
    if (tid == 0) {
        int need = NT - cnt;
        int m = eqcnt < 64 ? eqcnt : 64;
        for (int i = 1; i < m; i++) {
            int key = eqlist[i]; int j = i - 1;
            while (j >= 0 && eqlist[j] > key) { eqlist[j + 1] = eqlist[j]; j--; }
            eqlist[j + 1] = key;
        }
        float tv = __uint_as_float((thresh & 0x80000000u) ? (thresh & 0x7FFFFFFFu) : ~thresh);
        for (int r = 0; r < need && r < m; r++) {
            so[cnt + r] = tv;
            io[cnt + r] = eqlist[r];
        }
    }
}

// =====================================================================
// Kernel 3: bf16-split QKV GEMM on HMMA, cp.async double-buffered.
// =====================================================================
constexpr int TILEB = 8192;
constexpr int STAGEB = 4 * TILEB;
__global__ void __launch_bounds__(256) tc_gemm_kernel() {
    extern __shared__ __align__(128) char smem_raw[];

    const int m0 = blockIdx.x * 128;
    const int n0 = blockIdx.y * 128;
    const int b  = blockIdx.z;
    const int tid = threadIdx.x;
    const int wrp = tid >> 5, lane = tid & 31;
    const int wm = wrp >> 2, wn = wrp & 3;

    const uint32_t sbase = smem_u32(smem_raw);
    const size_t xbase = (size_t)b * NHW * NC;

    const int lj = lane >> 3, lr = lane & 7;
    const int a_row = wm * 64 + (lj & 1) * 8 + lr;
    const int a_j0  = lj >> 1;
    const int b_row = wn * 32 + (lj >> 1) * 8 + lr;
    const int b_j0  = lj & 1;

    float acc[4][4][4];
#pragma unroll
    for (int i = 0; i < 4; i++)
#pragma unroll
        for (int j = 0; j < 4; j++)
#pragma unroll
            for (int r = 0; r < 4; r++) acc[i][j][r] = 0.f;

    auto load_stage = [&](int stage, int k0) {
        const uint32_t sb = sbase + stage * STAGEB;
#pragma unroll
        for (int i = 0; i < 8; i++) {
            const int arr = i >> 1;
            const int rem = ((i & 1) << 8) + tid;
            const int r = rem >> 2, c = rem & 3;
            uint32_t dst = sb + arr * TILEB + r * 64 + ((c ^ ((r >> 1) & 3)) << 4);
            const __nv_bfloat16* src;
            if (arr == 0)      src = g_wh + (size_t)(m0 + r) * NC + k0;
            else if (arr == 1) src = g_wl + (size_t)(m0 + r) * NC + k0;
            else if (arr == 2) src = g_xh + xbase + (size_t)(n0 + r) * NC + k0;
            else               src = g_xl + xbase + (size_t)(n0 + r) * NC + k0;
            cp16(dst, src + c * 8);
        }
        CP_COMMIT();
    };

    load_stage(0, 0);

    for (int kc = 0; kc < 8; kc++) {
        if (kc < 7) load_stage((kc + 1) & 1, (kc + 1) * 32);
        if (kc < 7) cp_wait<1>(); else cp_wait<0>();
        __syncthreads();

        const uint32_t sb = sbase + (kc & 1) * STAGEB;
        const uint32_t bAh = sb, bAl = sb + TILEB, bBh = sb + 2 * TILEB, bBl = sb + 3 * TILEB;

#pragma unroll
        for (int ks = 0; ks < 2; ks++) {
            uint32_t bh[2][4], bl[2][4];
#pragma unroll
            for (int bt = 0; bt < 2; bt++) {
                int r = b_row + bt * 16;
                int j = b_j0 + ks * 2;
                uint32_t off = (uint32_t)(r * 64 + ((j ^ ((r >> 1) & 3)) << 4));
                ldsm4(bh[bt], bBh + off);
                ldsm4(bl[bt], bBl + off);
            }
#pragma unroll
            for (int mt = 0; mt < 4; mt++) {
                int r = a_row + mt * 16;
                int j = a_j0 + ks * 2;
                uint32_t off = (uint32_t)(r * 64 + ((j ^ ((r >> 1) & 3)) << 4));
                uint32_t ah[4], al[4];
                ldsm4(ah, bAh + off);
                ldsm4(al, bAl + off);
#pragma unroll
                for (int bt = 0; bt < 2; bt++)
#pragma unroll
                    for (int sub = 0; sub < 2; sub++) {
                        int nt = bt * 2 + sub;
                        mma16816(acc[mt][nt], ah, &bh[bt][sub * 2]);
                        mma16816(acc[mt][nt], al, &bh[bt][sub * 2]);
                        mma16816(acc[mt][nt], ah, &bl[bt][sub * 2]);
                    }
            }
        }
        __syncthreads();
    }

    float* ep = (float*)smem_raw;
    const int g = lane >> 2, q = lane & 3;
    for (int ci = 0; ci < 4; ci++) {
        if (wn == ci) {
#pragma unroll
            for (int mt = 0; mt < 4; mt++)
#pragma unroll
                for (int nt = 0; nt < 4; nt++) {
                    int nn = nt * 8 + 2 * q;
                    int m  = wm * 64 + mt * 16 + g;
                    ep[nn * 132 + m]           = acc[mt][nt][0];
                    ep[(nn + 1) * 132 + m]     = acc[mt][nt][1];
                    ep[nn * 132 + m + 8]       = acc[mt][nt][2];
                    ep[(nn + 1) * 132 + m + 8] = acc[mt][nt][3];
                }
        }
        __syncthreads();

        int nrow = tid >> 3, seg = (tid & 7) * 16;
        int n = n0 + ci * 32 + nrow;
        const float* src = ep + nrow * 132 + seg;
        float* ydst = g_yt + ((size_t)b * NHW + n) * MTOT + m0 + seg;
#pragma unroll
        for (int i = 0; i < 16; i += 4)
            *(float4*)(ydst + i) = make_float4(src[i], src[i + 1], src[i + 2], src[i + 3]);
        if (m0 >= 512) {
            float* adst = g_acc + ((size_t)b * NHW + n) * NC + (m0 - 512) + seg;
#pragma unroll
            for (int i = 0; i < 16; i += 4)
                *(float4*)(adst + i) = make_float4(src[i], src[i + 1], src[i + 2], src[i + 3]);
        }
        __syncthreads();
    }
}

// =====================================================================
// Kernel 4: HMMA attention per (s, head, b) tile.
//   4 warps, each owns 32 t-rows. bf16 hi/lo split for S and PV (3 terms).
//   Full 32x128 scores in registers, single-pass softmax.
//   Smem: Qh Ql Kh Kl Vh Vl (8KB each, XOR-swizzled 64B rows) + idx/sims.
// =====================================================================
constexpr int ATT_SMEM = 50176;
__global__ void __launch_bounds__(128) attn_kernel() {
    extern __shared__ __align__(128) char SM[];
    const int s = blockIdx.x, h = blockIdx.y, b = blockIdx.z;
    const int tid = threadIdx.x, lane = tid & 31, wrp = tid >> 5;

    char* QH = SM;            char* QL = SM + 8192;
    char* KH = SM + 16384;    char* KL = SM + 24576;
    char* VH = SM + 32768;    char* VL = SM + 40960;
    int*   idxs = (int*)(SM + 49152);
    float* simv = (float*)(SM + 49664);

    {
        const int gi = (b * NS + s) * NT + tid;
        idxs[tid] = g_idx[gi];
        simv[tid] = g_sims[gi];
    }
    __syncthreads();

    // ---- gather + bf16 hi/lo convert (warp-cooperative, coalesced) ----
#pragma unroll 4
    for (int rr = 0; rr < 32; rr++) {
        int r = wrp * 32 + rr;
        const float* yrow = g_yt + ((size_t)b * NHW + idxs[r]) * MTOT + h * NDH;
        float sim = simv[r];
        float q = yrow[lane];
        float k = yrow[256 + lane];
        float v = yrow[512 + lane] * sim;
        int chunk = lane >> 3;
        uint32_t off = (uint32_t)(r * 64 + ((chunk ^ ((r >> 1) & 3)) << 4) + (lane & 7) * 2);
        __nv_bfloat16 qh = __float2bfloat16_rn(q);
        __nv_bfloat16 kh = __float2bfloat16_rn(k);
        __nv_bfloat16 vh = __float2bfloat16_rn(v);
        *(__nv_bfloat16*)(QH + off) = qh;
        *(__nv_bfloat16*)(QL + off) = __float2bfloat16_rn(q - __bfloat162float(qh));
        *(__nv_bfloat16*)(KH + off) = kh;
        *(__nv_bfloat16*)(KL + off) = __float2bfloat16_rn(k - __bfloat162float(kh));
        *(__nv_bfloat16*)(VH + off) = vh;
        *(__nv_bfloat16*)(VL + off) = __float2bfloat16_rn(v - __bfloat162float(vh));
    }
    __syncthreads();

    const uint32_t uQH = smem_u32(QH), uQL = smem_u32(QL),
                   uKH = smem_u32(KH), uKL = smem_u32(KL),
                   uVH = smem_u32(VH), uVL = smem_u32(VL);

    const int lrow = ((lane >> 3) & 1) * 8 + (lane & 7);   // ldsm row within 16
    const int lchk = lane >> 4;                             // ldsm chunk sel 0/1

    // ---- scores S[32t x 128u] ----
    float sc[2][16][4];
#pragma unroll
    for (int mt = 0; mt < 2; mt++)
#pragma unroll
        for (int nt = 0; nt < 16; nt++)
#pragma unroll
            for (int j = 0; j < 4; j++) sc[mt][nt][j] = 0.f;

#pragma unroll
    for (int kc = 0; kc < 2; kc++) {
        uint32_t aqh[2][4], aql[2][4];
#pragma unroll
        for (int mt = 0; mt < 2; mt++) {
            int r = wrp * 32 + mt * 16 + lrow;
            int chunk = 2 * kc + lchk;
            uint32_t off = (uint32_t)(r * 64 + ((chunk ^ ((r >> 1) & 3)) << 4));
            ldsm4(aqh[mt], uQH + off);
            ldsm4(aql[mt], uQL + off);
        }
#pragma unroll
        for (int un = 0; un < 8; un++) {
            int r = un * 16 + lrow;
            int chunk = 2 * kc + lchk;
            uint32_t off = (uint32_t)(r * 64 + ((chunk ^ ((r >> 1) & 3)) << 4));
            uint32_t kh4[4], kl4[4];
            ldsm4(kh4, uKH + off);
            ldsm4(kl4, uKL + off);
#pragma unroll
            for (int mt = 0; mt < 2; mt++)
#pragma unroll
                for (int sub = 0; sub < 2; sub++) {
                    float* d = sc[mt][un * 2 + sub];
                    mma16816b(d, aqh[mt], kh4[sub], kh4[sub + 2]);
                    mma16816b(d, aql[mt], kh4[sub], kh4[sub + 2]);
                    mma16816b(d, aqh[mt], kl4[sub], kl4[sub + 2]);
                }
        }
    }

    // ---- softmax (rows live in lane quads; reduce via shfl xor 1,2) ----
    float linv[2][2];
#pragma unroll
    for (int mt = 0; mt < 2; mt++) {
        float m0 = -1e30f, m1 = -1e30f;
#pragma unroll
        for (int nt = 0; nt < 16; nt++) {
            m0 = fmaxf(m0, fmaxf(sc[mt][nt][0], sc[mt][nt][1]));
            m1 = fmaxf(m1, fmaxf(sc[mt][nt][2], sc[mt][nt][3]));
        }
        m0 = fmaxf(m0, __shfl_xor_sync(0xFFFFFFFFu, m0, 1));
        m0 = fmaxf(m0, __shfl_xor_sync(0xFFFFFFFFu, m0, 2));
        m1 = fmaxf(m1, __shfl_xor_sync(0xFFFFFFFFu, m1, 1));
        m1 = fmaxf(m1, __shfl_xor_sync(0xFFFFFFFFu, m1, 2));
        float s0 = 0.f, s1 = 0.f;
#pragma unroll
        for (int nt = 0; nt < 16; nt++) {
            sc[mt][nt][0] = __expf((sc[mt][nt][0] - m0) * ATT_SCALE);
            sc[mt][nt][1] = __expf((sc[mt][nt][1] - m0) * ATT_SCALE);
            sc[mt][nt][2] = __expf((sc[mt][nt][2] - m1) * ATT_SCALE);
            sc[mt][nt][3] = __expf((sc[mt][nt][3] - m1) * ATT_SCALE);
            s0 += sc[mt][nt][0] + sc[mt][nt][1];
            s1 += sc[mt][nt][2] + sc[mt][nt][3];
        }
        s0 += __shfl_xor_sync(0xFFFFFFFFu, s0, 1);
        s0 += __shfl_xor_sync(0xFFFFFFFFu, s0, 2);
        s1 += __shfl_xor_sync(0xFFFFFFFFu, s1, 1);
        s1 += __shfl_xor_sync(0xFFFFFFFFu, s1, 2);
        linv[mt][0] = 1.0f / s0;
        linv[mt][1] = 1.0f / s1;
    }

    // ---- PV: out[32t x 32c] = P(32x128) * Vw(128x32), 3 split terms ----
    float out[2][4][4];
#pragma unroll
    for (int mt = 0; mt < 2; mt++)
#pragma unroll
        for (int nt = 0; nt < 4; nt++)
#pragma unroll
            for (int j = 0; j < 4; j++) out[mt][nt][j] = 0.f;

#pragma unroll
    for (int kt = 0; kt < 8; kt++) {
        uint32_t vha[4], vla[4], vhb[4], vlb[4];
        {
            int r = kt * 16 + lrow;
            int sw = (r >> 1) & 3;
            uint32_t offa = (uint32_t)(r * 64 + (((0 + lchk) ^ sw) << 4));
            uint32_t offb = (uint32_t)(r * 64 + (((2 + lchk) ^ sw) << 4));
            ldsm4t(vha, uVH + offa);
            ldsm4t(vla, uVL + offa);
            ldsm4t(vhb, uVH + offb);
            ldsm4t(vlb, uVL + offb);
        }
#pragma unroll
        for (int mt = 0; mt < 2; mt++) {
            uint32_t ph[4], pl[4];
            hilo2(sc[mt][2 * kt][0],     sc[mt][2 * kt][1],     ph[0], pl[0]);
            hilo2(sc[mt][2 * kt][2],     sc[mt][2 * kt][3],     ph[1], pl[1]);
            hilo2(sc[mt][2 * kt + 1][0], sc[mt][2 * kt + 1][1], ph[2], pl[2]);
            hilo2(sc[mt][2 * kt + 1][2], sc[mt][2 * kt + 1][3], ph[3], pl[3]);
            mma16816(out[mt][0], ph, &vha[0]);
            mma16816(out[mt][0], pl, &vha[0]);
            mma16816b(out[mt][0], ph, vla[0], vla[1]);
            mma16816b(out[mt][1], ph, vha[2], vha[3]);
            mma16816b(out[mt][1], pl, vha[2], vha[3]);
            mma16816b(out[mt][1], ph, vla[2], vla[3]);
            mma16816(out[mt][2], ph, &vhb[0]);
            mma16816(out[mt][2], pl, &vhb[0]);
            mma16816b(out[mt][2], ph, vlb[0], vlb[1]);
            mma16816b(out[mt][3], ph, vhb[2], vhb[3]);
            mma16816b(out[mt][3], pl, vhb[2], vhb[3]);
            mma16816b(out[mt][3], ph, vlb[2], vlb[3]);
        }
    }

    // ---- epilogue: scale by sim_t/l_t, stage, coalesced atomic scatter ----
    __syncthreads();
    float* stage = (float*)SM;     // [128][33] floats (16.9 KB, clears Q/K only)
#pragma unroll
    for (int mt = 0; mt < 2; mt++) {
        int r0 = wrp * 32 + mt * 16 + (lane >> 2);
        float f0 = simv[r0] * linv[mt][0];
        float f1 = simv[r0 + 8] * linv[mt][1];
#pragma unroll
        for (int ntc = 0; ntc < 4; ntc++) {
            int c = ntc * 8 + 2 * (lane & 3);
            stage[r0 * 33 + c]           = out[mt][ntc][0] * f0;
            stage[r0 * 33 + c + 1]       = out[mt][ntc][1] * f0;
            stage[(r0 + 8) * 33 + c]     = out[mt][ntc][2] * f1;
            stage[(r0 + 8) * 33 + c + 1] = out[mt][ntc][3] * f1;
        }
    }
    __syncthreads();
#pragma unroll 4
    for (int r = 0; r < 32; r++) {
        int tt = r * 4 + wrp;
        atomicAdd(&g_acc[((size_t)b * NHW + idxs[tt]) * NC + h * NDH + lane],
                  stage[tt * 33 + lane]);
    }
}

// =====================================================================
// Kernel 5: transpose accumulator (B, HW, C) -> out (B, C, HW)
// =====================================================================
__global__ void __launch_bounds__(256) transpose_kernel(float* __restrict__ out) {
    __shared__ float tile[32][33];
    const int b  = blockIdx.z;
    const int n0 = blockIdx.x * 32;
    const int c0 = blockIdx.y * 32;
    const int tx = threadIdx.x, ty = threadIdx.y;
#pragma unroll
    for (int j = 0; j < 32; j += 8)
        tile[ty + j][tx] = g_acc[((size_t)b * NHW + n0 + ty + j) * NC + c0 + tx];
    __syncthreads();
#pragma unroll
    for (int j = 0; j < 32; j += 8)
        out[((size_t)b * NC + c0 + ty + j) * NHW + n0 + tx] = tile[tx][ty + j];
}

// =====================================================================
extern "C" void kernel_launch(void* const* d_in, const int* in_sizes, int n_in,
                              void* d_out, int out_size) {
    const float* x    = (const float*)d_in[0];
    const float* aff  = (const float*)d_in[1];
    const float* lnw  = (const float*)d_in[2];
    const float* lnb  = (const float*)d_in[3];
    const float* wq   = (const float*)d_in[4];
    const float* wk   = (const float*)d_in[5];
    const float* wv   = (const float*)d_in[6];
    float* out = (float*)d_out;

    cudaFuncSetAttribute(tc_gemm_kernel,
                         cudaFuncAttributeMaxDynamicSharedMemorySize, 2 * STAGEB);
    cudaFuncSetAttribute(attn_kernel,
                         cudaFuncAttributeMaxDynamicSharedMemorySize, ATT_SMEM);

    ln_stats_kernel<<<(NB * NHW) / 256, 256>>>(x);
    xsplit_kernel<<<dim3(NHW / 32, NC / 32, NB), dim3(32, 8)>>>(x, lnw, lnb);
    wsplit_kernel<<<MTOT, 256>>>(wq, wk, wv);
    topk_kernel<<<NB * NS, 512>>>(aff);
    tc_gemm_kernel<<<dim3(MTOT / 128, NHW / 128, NB), 256, 2 * STAGEB>>>();
    attn_kernel<<<dim3(NS, NHEADS, NB), 128, ATT_SMEM>>>();
    transpose_kernel<<<dim3(NHW / 32, NC / 32, NB), dim3(32, 8)>>>(out);
}

// round 9
// speedup vs baseline: 2.7310x; 1.5494x over previous
#include <cuda_runtime.h>
#include <cuda_bf16.h>
#include <cstdint>
#include <math.h>

// ---------------- problem constants ----------------
constexpr int NB     = 2;
constexpr int NC     = 256;     // channels (= QK)
constexpr int NHW    = 16384;   // H*W
constexpr int NS     = 256;     // superpixels
constexpr int NT     = 128;     // top-k
constexpr int NHEADS = 8;
constexpr int NDH    = 32;      // head dim
constexpr int MTOT   = 768;     // q(256) + k(256) + v(256)
constexpr float EPSV      = 1e-5f;
constexpr float ATT_SCALE = 0.17677669529663687f;  // 1/sqrt(32)

// ---------------- scratch (device globals; no allocations allowed) ----------
__device__ __nv_bfloat16 g_ybh[(size_t)NB * NHW * MTOT]; // qkv hi, n-major
__device__ __nv_bfloat16 g_ybl[(size_t)NB * NHW * MTOT]; // qkv lo
__device__ float  g_acc[(size_t)NB * NHW * NC];          // output accumulator (n-major)
__device__ float  g_sims[NB * NS * NT];
__device__ int    g_idx [NB * NS * NT];
__device__ float2 g_stat[NB * NHW];                      // (mu, inv) per pixel
__device__ __nv_bfloat16 g_xh[(size_t)NB * NHW * NC];    // ln(x) hi, [b][n][c]
__device__ __nv_bfloat16 g_xl[(size_t)NB * NHW * NC];    // ln(x) lo
__device__ __nv_bfloat16 g_wh[MTOT * NC];                // stacked W hi
__device__ __nv_bfloat16 g_wl[MTOT * NC];                // stacked W lo

// ---------------- PTX helpers (baseline ISA only, valid on compute_103) ----
__device__ __forceinline__ uint32_t smem_u32(const void* p) {
    uint32_t a;
    asm("{ .reg .u64 t; cvta.to.shared.u64 t, %1; cvt.u32.u64 %0, t; }" : "=r"(a) : "l"(p));
    return a;
}
__device__ __forceinline__ void ldsm4(uint32_t* r, uint32_t addr) {
    asm volatile("ldmatrix.sync.aligned.m8n8.x4.shared.b16 {%0,%1,%2,%3}, [%4];"
                 : "=r"(r[0]), "=r"(r[1]), "=r"(r[2]), "=r"(r[3]) : "r"(addr));
}
__device__ __forceinline__ void ldsm4t(uint32_t* r, uint32_t addr) {
    asm volatile("ldmatrix.sync.aligned.m8n8.x4.trans.shared.b16 {%0,%1,%2,%3}, [%4];"
                 : "=r"(r[0]), "=r"(r[1]), "=r"(r[2]), "=r"(r[3]) : "r"(addr));
}
__device__ __forceinline__ void mma16816(float* d, const uint32_t* a, const uint32_t* b) {
    asm volatile("mma.sync.aligned.m16n8k16.row.col.f32.bf16.bf16.f32 "
                 "{%0,%1,%2,%3}, {%4,%5,%6,%7}, {%8,%9}, {%0,%1,%2,%3};"
                 : "+f"(d[0]), "+f"(d[1]), "+f"(d[2]), "+f"(d[3])
                 : "r"(a[0]), "r"(a[1]), "r"(a[2]), "r"(a[3]), "r"(b[0]), "r"(b[1]));
}
__device__ __forceinline__ void mma16816b(float* d, const uint32_t* a, uint32_t b0, uint32_t b1) {
    asm volatile("mma.sync.aligned.m16n8k16.row.col.f32.bf16.bf16.f32 "
                 "{%0,%1,%2,%3}, {%4,%5,%6,%7}, {%8,%9}, {%0,%1,%2,%3};"
                 : "+f"(d[0]), "+f"(d[1]), "+f"(d[2]), "+f"(d[3])
                 : "r"(a[0]), "r"(a[1]), "r"(a[2]), "r"(a[3]), "r"(b0), "r"(b1));
}
__device__ __forceinline__ void cp16(uint32_t dst, const void* src) {
    asm volatile("{ .reg .u64 g; cvta.to.global.u64 g, %1; cp.async.ca.shared.global [%0], [g], 16; }"
                 :: "r"(dst), "l"(src) : "memory");
}
#define CP_COMMIT() asm volatile("cp.async.commit_group;" ::: "memory")
template <int N>
__device__ __forceinline__ void cp_wait() {
    asm volatile("cp.async.wait_group %0;" :: "n"(N) : "memory");
}
__device__ __forceinline__ void hilo2(float a, float b, uint32_t& hi, uint32_t& lo) {
    __nv_bfloat16 ah = __float2bfloat16_rn(a), bh = __float2bfloat16_rn(b);
    __nv_bfloat162 hp; hp.x = ah; hp.y = bh;
    __nv_bfloat162 lp;
    lp.x = __float2bfloat16_rn(a - __bfloat162float(ah));
    lp.y = __float2bfloat16_rn(b - __bfloat162float(bh));
    hi = *(uint32_t*)&hp;
    lo = *(uint32_t*)&lp;
}

// =====================================================================
// Kernel 1a: LayerNorm statistics per pixel (coalesced over n).
// =====================================================================
__global__ void __launch_bounds__(256) ln_stats_kernel(const float* __restrict__ x) {
    int p = blockIdx.x * blockDim.x + threadIdx.x;
    int b = p / NHW;
    int n = p - b * NHW;
    const float* xb = x + (size_t)b * NC * NHW + n;
    float s = 0.f, ss = 0.f;
#pragma unroll 8
    for (int c = 0; c < NC; c++) {
        float v = xb[(size_t)c * NHW];
        s += v; ss += v * v;
    }
    float mu  = s * (1.0f / NC);
    float var = ss * (1.0f / NC) - mu * mu;
    g_stat[p] = make_float2(mu, rsqrtf(var + EPSV));
}

// =====================================================================
// Kernel 1b: normalize + transpose to [b][n][c] + bf16 hi/lo split.
// =====================================================================
__global__ void __launch_bounds__(256) xsplit_kernel(const float* __restrict__ x,
                                                     const float* __restrict__ lw,
                                                     const float* __restrict__ lb) {
    __shared__ float tile[32][33];
    const int b  = blockIdx.z;
    const int n0 = blockIdx.x * 32;
    const int c0 = blockIdx.y * 32;
    const int tx = threadIdx.x, ty = threadIdx.y;
#pragma unroll
    for (int j = 0; j < 32; j += 8)
        tile[ty + j][tx] = x[((size_t)b * NC + c0 + ty + j) * NHW + n0 + tx];
    __syncthreads();
    const float w = lw[c0 + tx], bi = lb[c0 + tx];
#pragma unroll
    for (int j = 0; j < 32; j += 8) {
        int n = n0 + ty + j;
        float2 st = g_stat[b * NHW + n];
        float v = (tile[tx][ty + j] - st.x) * st.y * w + bi;
        __nv_bfloat16 hi = __float2bfloat16_rn(v);
        __nv_bfloat16 lo = __float2bfloat16_rn(v - __bfloat162float(hi));
        size_t o = ((size_t)b * NHW + n) * NC + c0 + tx;
        g_xh[o] = hi;
        g_xl[o] = lo;
    }
}

// =====================================================================
// Kernel 1c: split stacked W (wq;wk;wv) into bf16 hi/lo.
// =====================================================================
__global__ void __launch_bounds__(256) wsplit_kernel(const float* __restrict__ wq,
                                                     const float* __restrict__ wk,
                                                     const float* __restrict__ wv) {
    int m = blockIdx.x, c = threadIdx.x;
    const float* src = (m < 256) ? (wq + (size_t)m * NC)
                     : (m < 512) ? (wk + (size_t)(m - 256) * NC)
                                 : (wv + (size_t)(m - 512) * NC);
    float v = src[c];
    __nv_bfloat16 hi = __float2bfloat16_rn(v);
    __nv_bfloat16 lo = __float2bfloat16_rn(v - __bfloat162float(hi));
    g_wh[(size_t)m * NC + c] = hi;
    g_wl[(size_t)m * NC + c] = lo;
}

// =====================================================================
// Kernel 2: exact top-128 per row (warp-aggregated radix select).
// =====================================================================
__device__ __forceinline__ unsigned f2k(float f) {
    unsigned u = __float_as_uint(f);
    return (u & 0x80000000u) ? ~u : (u | 0x80000000u);
}
constexpr int TCAP = 4096;

__global__ void __launch_bounds__(512) topk_kernel(const float* __restrict__ aff) {
    const int row = blockIdx.x;
    const float* a = aff + (size_t)row * NHW;
    const int tid = threadIdx.x, lane = tid & 31;

    __shared__ unsigned hist[256];
    __shared__ float candV[TCAP];
    __shared__ int   candI[TCAP];
    __shared__ unsigned sh_digit, sh_rem;
    __shared__ int cnt, nc, eqcnt;
    __shared__ int eqlist[64];

    for (int i = tid; i < 256; i += 512) hist[i] = 0;
    if (tid == 0) { cnt = 0; nc = 0; eqcnt = 0; }
    __syncthreads();

    for (int i = tid; i < NHW; i += 512) {
        unsigned byte = f2k(a[i]) >> 24;
        unsigned m = __match_any_sync(0xFFFFFFFFu, byte);
        if ((int)(__ffs(m) - 1) == lane) atomicAdd(&hist[byte], __popc(m));
    }
    __syncthreads();
    if (tid == 0) {
        unsigned r = NT;
        int d = 255;
        for (; d > 0; d--) {
            unsigned c = hist[d];
            if (c >= r) break;
            r -= c;
        }
        sh_digit = (unsigned)d;
        sh_rem = r;
    }
    __syncthreads();
    const unsigned dtop = sh_digit;
    unsigned rem = sh_rem;

    float* so = g_sims + (size_t)row * NT;
    int*   io = g_idx  + (size_t)row * NT;

    for (int i = tid; i < NHW; i += 512) {
        float v = a[i];
        unsigned byte = f2k(v) >> 24;
        if (byte > dtop) {
            int p = atomicAdd(&cnt, 1);
            so[p] = v; io[p] = i;
        } else if (byte == dtop) {
            int q = atomicAdd(&nc, 1);
            if (q < TCAP) { candV[q] = v; candI[q] = i; }
        }
    }
    __syncthreads();

    unsigned prefix  = dtop << 24;
    unsigned prefmask = 0xFF000000u;
    const bool incache = (nc <= TCAP);
    const int ncand = incache ? nc : 0;

    for (int shift = 16; shift >= 0; shift -= 8) {
        for (int i = tid; i < 256; i += 512) hist[i] = 0;
        __syncthreads();
        if (incache) {
            for (int j = tid; j < ncand; j += 512) {
                unsigned key = f2k(candV[j]);
                if ((key & prefmask) == prefix) {
                    unsigned byte = (key >> shift) & 255u;
                    unsigned m = __match_any_sync(__activemask(), byte);
                    if ((int)(__ffs(m) - 1) == lane) atomicAdd(&hist[byte], __popc(m));
                }
            }
        } else {
            for (int i = tid; i < NHW; i += 512) {
                unsigned key = f2k(a[i]);
                if ((key & prefmask) == prefix) {
                    unsigned byte = (key >> shift) & 255u;
                    unsigned m = __match_any_sync(__activemask(), byte);
                    if ((int)(__ffs(m) - 1) == lane) atomicAdd(&hist[byte], __popc(m));
                }
            }
        }
        __syncthreads();
        if (tid == 0) {
            unsigned r = rem;
            int d = 255;
            for (; d > 0; d--) {
                unsigned c = hist[d];
                if (c >= r) break;
                r -= c;
            }
            sh_digit = (unsigned)d;
            sh_rem = r;
        }
        __syncthreads();
        prefix   |= (sh_digit << shift);
        prefmask |= (0xFFu << shift);
        rem = sh_rem;
        __syncthreads();
    }

    const unsigned thresh = prefix;
    if (incache) {
        for (int j = tid; j < ncand; j += 512) {
            unsigned key = f2k(candV[j]);
            if (key > thresh) {
                int p = atomicAdd(&cnt, 1);
                so[p] = candV[j]; io[p] = candI[j];
            } else if (key == thresh) {
                int p = atomicAdd(&eqcnt, 1);
                if (p < 64) eqlist[p] = candI[j];
            }
        }
    } else {
        for (int i = tid; i < NHW; i += 512) {
            float v = a[i];
            unsigned key = f2k(v);
            if (key > thresh && (key >> 24) == dtop) {
                int p = atomicAdd(&cnt, 1);
                so[p] = v; io[p] = i;
            } else if (key == thresh) {
                int p = atomicAdd(&eqcnt, 1);
                if (p < 64) eqlist[p] = i;
            }
        }
    }
    __syncthreads();
    if (tid == 0) {
        int need = NT - cnt;
        int m = eqcnt < 64 ? eqcnt : 64;
        for (int i = 1; i < m; i++) {
            int key = eqlist[i]; int j = i - 1;
            while (j >= 0 && eqlist[j] > key) { eqlist[j + 1] = eqlist[j]; j--; }
            eqlist[j + 1] = key;
        }
        float tv = __uint_as_float((thresh & 0x80000000u) ? (thresh & 0x7FFFFFFFu) : ~thresh);
        for (int r = 0; r < need && r < m; r++) {
            so[cnt + r] = tv;
            io[cnt + r] = eqlist[r];
        }
    }
}

// =====================================================================
// Kernel 3: bf16-split QKV GEMM on HMMA, cp.async double-buffered.
//   Epilogue now writes qkv as bf16 hi/lo (g_ybh/g_ybl) + fp32 g_acc seed.
// =====================================================================
constexpr int TILEB = 8192;
constexpr int STAGEB = 4 * TILEB;
__global__ void __launch_bounds__(256) tc_gemm_kernel() {
    extern __shared__ __align__(128) char smem_raw[];

    const int m0 = blockIdx.x * 128;
    const int n0 = blockIdx.y * 128;
    const int b  = blockIdx.z;
    const int tid = threadIdx.x;
    const int wrp = tid >> 5, lane = tid & 31;
    const int wm = wrp >> 2, wn = wrp & 3;

    const uint32_t sbase = smem_u32(smem_raw);
    const size_t xbase = (size_t)b * NHW * NC;

    const int lj = lane >> 3, lr = lane & 7;
    const int a_row = wm * 64 + (lj & 1) * 8 + lr;
    const int a_j0  = lj >> 1;
    const int b_row = wn * 32 + (lj >> 1) * 8 + lr;
    const int b_j0  = lj & 1;

    float acc[4][4][4];
#pragma unroll
    for (int i = 0; i < 4; i++)
#pragma unroll
        for (int j = 0; j < 4; j++)
#pragma unroll
            for (int r = 0; r < 4; r++) acc[i][j][r] = 0.f;

    auto load_stage = [&](int stage, int k0) {
        const uint32_t sb = sbase + stage * STAGEB;
#pragma unroll
        for (int i = 0; i < 8; i++) {
            const int arr = i >> 1;
            const int rem = ((i & 1) << 8) + tid;
            const int r = rem >> 2, c = rem & 3;
            uint32_t dst = sb + arr * TILEB + r * 64 + ((c ^ ((r >> 1) & 3)) << 4);
            const __nv_bfloat16* src;
            if (arr == 0)      src = g_wh + (size_t)(m0 + r) * NC + k0;
            else if (arr == 1) src = g_wl + (size_t)(m0 + r) * NC + k0;
            else if (arr == 2) src = g_xh + xbase + (size_t)(n0 + r) * NC + k0;
            else               src = g_xl + xbase + (size_t)(n0 + r) * NC + k0;
            cp16(dst, src + c * 8);
        }
        CP_COMMIT();
    };

    load_stage(0, 0);

    for (int kc = 0; kc < 8; kc++) {
        if (kc < 7) load_stage((kc + 1) & 1, (kc + 1) * 32);
        if (kc < 7) cp_wait<1>(); else cp_wait<0>();
        __syncthreads();

        const uint32_t sb = sbase + (kc & 1) * STAGEB;
        const uint32_t bAh = sb, bAl = sb + TILEB, bBh = sb + 2 * TILEB, bBl = sb + 3 * TILEB;

#pragma unroll
        for (int ks = 0; ks < 2; ks++) {
            uint32_t bh[2][4], bl[2][4];
#pragma unroll
            for (int bt = 0; bt < 2; bt++) {
                int r = b_row + bt * 16;
                int j = b_j0 + ks * 2;
                uint32_t off = (uint32_t)(r * 64 + ((j ^ ((r >> 1) & 3)) << 4));
                ldsm4(bh[bt], bBh + off);
                ldsm4(bl[bt], bBl + off);
            }
#pragma unroll
            for (int mt = 0; mt < 4; mt++) {
                int r = a_row + mt * 16;
                int j = a_j0 + ks * 2;
                uint32_t off = (uint32_t)(r * 64 + ((j ^ ((r >> 1) & 3)) << 4));
                uint32_t ah[4], al[4];
                ldsm4(ah, bAh + off);
                ldsm4(al, bAl + off);
#pragma unroll
                for (int bt = 0; bt < 2; bt++)
#pragma unroll
                    for (int sub = 0; sub < 2; sub++) {
                        int nt = bt * 2 + sub;
                        mma16816(acc[mt][nt], ah, &bh[bt][sub * 2]);
                        mma16816(acc[mt][nt], al, &bh[bt][sub * 2]);
                        mma16816(acc[mt][nt], ah, &bl[bt][sub * 2]);
                    }
            }
        }
        __syncthreads();
    }

    float* ep = (float*)smem_raw;
    const int g = lane >> 2, q = lane & 3;
    for (int ci = 0; ci < 4; ci++) {
        if (wn == ci) {
#pragma unroll
            for (int mt = 0; mt < 4; mt++)
#pragma unroll
                for (int nt = 0; nt < 4; nt++) {
                    int nn = nt * 8 + 2 * q;
                    int m  = wm * 64 + mt * 16 + g;
                    ep[nn * 132 + m]           = acc[mt][nt][0];
                    ep[(nn + 1) * 132 + m]     = acc[mt][nt][1];
                    ep[nn * 132 + m + 8]       = acc[mt][nt][2];
                    ep[(nn + 1) * 132 + m + 8] = acc[mt][nt][3];
                }
        }
        __syncthreads();

        int nrow = tid >> 3, seg = (tid & 7) * 16;
        int n = n0 + ci * 32 + nrow;
        const float* src = ep + nrow * 132 + seg;
        size_t yo = ((size_t)b * NHW + n) * MTOT + m0 + seg;
        __nv_bfloat16 hb[16], lb[16];
#pragma unroll
        for (int i = 0; i < 16; i++) {
            float v = src[i];
            hb[i] = __float2bfloat16_rn(v);
            lb[i] = __float2bfloat16_rn(v - __bfloat162float(hb[i]));
        }
        *(uint4*)(g_ybh + yo)     = *(uint4*)&hb[0];
        *(uint4*)(g_ybh + yo + 8) = *(uint4*)&hb[8];
        *(uint4*)(g_ybl + yo)     = *(uint4*)&lb[0];
        *(uint4*)(g_ybl + yo + 8) = *(uint4*)&lb[8];
        if (m0 >= 512) {
            float* adst = g_acc + ((size_t)b * NHW + n) * NC + (m0 - 512) + seg;
#pragma unroll
            for (int i = 0; i < 16; i += 4)
                *(float4*)(adst + i) = make_float4(src[i], src[i + 1], src[i + 2], src[i + 3]);
        }
        __syncthreads();
    }
}

// =====================================================================
// Kernel 4: HMMA attention per (s, head, b) tile.
//   256 threads, 8 warps x 16 t-rows. cp.async gather (no conversion);
//   sims[u] folded into P; bf16 hi/lo 3-term split for S and PV.
// =====================================================================
constexpr int ATT_SMEM = 50176;   // 6 tiles * 8KB + idx + sims
__global__ void __launch_bounds__(256) attn_kernel() {
    extern __shared__ __align__(128) char SM[];
    const int s = blockIdx.x, h = blockIdx.y, b = blockIdx.z;
    const int tid = threadIdx.x, lane = tid & 31, wr = tid >> 5;

    int*   idxs = (int*)(SM + 49152);
    float* simv = (float*)(SM + 49664);

    if (tid < NT) {
        const int gi = (b * NS + s) * NT + tid;
        idxs[tid] = g_idx[gi];
        simv[tid] = g_sims[gi];
    }
    __syncthreads();

    const uint32_t tb = smem_u32(SM);
    const uint32_t uQH = tb, uQL = tb + 8192, uKH = tb + 16384, uKL = tb + 24576,
                   uVH = tb + 32768, uVL = tb + 40960;

    // ---- pure cp.async gather: 6 tiles x 128 rows x 4 x 16B ----
#pragma unroll
    for (int i = 0; i < 2; i++) {
        int r = i * 64 + (tid >> 2), c = tid & 3;
        uint32_t swoff = (uint32_t)(r * 64 + ((c ^ ((r >> 1) & 3)) << 4));
        size_t rowb = ((size_t)b * NHW + idxs[r]) * MTOT + h * 32 + c * 8;
#pragma unroll
        for (int ar = 0; ar < 3; ar++) {
            cp16(tb + ar * 16384 + swoff,        g_ybh + rowb + ar * 256);
            cp16(tb + ar * 16384 + 8192 + swoff, g_ybl + rowb + ar * 256);
        }
    }
    CP_COMMIT();
    cp_wait<0>();
    __syncthreads();

    const int lrow = ((lane >> 3) & 1) * 8 + (lane & 7);
    const int lchk = lane >> 4;

    // ---- scores S[16t x 128u], 3 split terms ----
    float sc[16][4];
#pragma unroll
    for (int nt = 0; nt < 16; nt++)
#pragma unroll
        for (int j = 0; j < 4; j++) sc[nt][j] = 0.f;

#pragma unroll
    for (int kc = 0; kc < 2; kc++) {
        int chunk = 2 * kc + lchk;
        int rq = wr * 16 + lrow;
        uint32_t offq = (uint32_t)(rq * 64 + ((chunk ^ ((rq >> 1) & 3)) << 4));
        uint32_t aqh[4], aql[4];
        ldsm4(aqh, uQH + offq);
        ldsm4(aql, uQL + offq);
#pragma unroll
        for (int un = 0; un < 8; un++) {
            int rk = un * 16 + lrow;
            uint32_t offk = (uint32_t)(rk * 64 + ((chunk ^ ((rk >> 1) & 3)) << 4));
            uint32_t kh4[4], kl4[4];
            ldsm4(kh4, uKH + offk);
            ldsm4(kl4, uKL + offk);
#pragma unroll
            for (int sub = 0; sub < 2; sub++) {
                float* d = sc[un * 2 + sub];
                mma16816b(d, aqh, kh4[sub], kh4[sub + 2]);
                mma16816b(d, aql, kh4[sub], kh4[sub + 2]);
                mma16816b(d, aqh, kl4[sub], kl4[sub + 2]);
            }
        }
    }

    // ---- softmax (rows in lane quads; reduce via shfl xor 1,2) ----
    float m0 = -1e30f, m1 = -1e30f;
#pragma unroll
    for (int nt = 0; nt < 16; nt++) {
        m0 = fmaxf(m0, fmaxf(sc[nt][0], sc[nt][1]));
        m1 = fmaxf(m1, fmaxf(sc[nt][2], sc[nt][3]));
    }
    m0 = fmaxf(m0, __shfl_xor_sync(0xFFFFFFFFu, m0, 1));
    m0 = fmaxf(m0, __shfl_xor_sync(0xFFFFFFFFu, m0, 2));
    m1 = fmaxf(m1, __shfl_xor_sync(0xFFFFFFFFu, m1, 1));
    m1 = fmaxf(m1, __shfl_xor_sync(0xFFFFFFFFu, m1, 2));
    float s0 = 0.f, s1 = 0.f;
#pragma unroll
    for (int nt = 0; nt < 16; nt++) {
        sc[nt][0] = __expf((sc[nt][0] - m0) * ATT_SCALE);
        sc[nt][1] = __expf((sc[nt][1] - m0) * ATT_SCALE);
        sc[nt][2] = __expf((sc[nt][2] - m1) * ATT_SCALE);
        sc[nt][3] = __expf((sc[nt][3] - m1) * ATT_SCALE);
        s0 += sc[nt][0] + sc[nt][1];
        s1 += sc[nt][2] + sc[nt][3];
    }
    s0 += __shfl_xor_sync(0xFFFFFFFFu, s0, 1);
    s0 += __shfl_xor_sync(0xFFFFFFFFu, s0, 2);
    s1 += __shfl_xor_sync(0xFFFFFFFFu, s1, 1);
    s1 += __shfl_xor_sync(0xFFFFFFFFu, s1, 2);
    const float linv0 = 1.0f / s0, linv1 = 1.0f / s1;

    // ---- fold sims[u] into P ----
#pragma unroll
    for (int nt = 0; nt < 16; nt++) {
        int u0 = nt * 8 + 2 * (lane & 3);
        float su0 = simv[u0], su1 = simv[u0 + 1];
        sc[nt][0] *= su0; sc[nt][1] *= su1;
        sc[nt][2] *= su0; sc[nt][3] *= su1;
    }

    // ---- PV: out[16t x 32c] = P(16x128) * V(128x32), 3 split terms ----
    float out[4][4];
#pragma unroll
    for (int nt = 0; nt < 4; nt++)
#pragma unroll
        for (int j = 0; j < 4; j++) out[nt][j] = 0.f;

#pragma unroll
    for (int kt = 0; kt < 8; kt++) {
        uint32_t vha[4], vla[4], vhb[4], vlb[4];
        {
            int rv = kt * 16 + lrow;
            int sw = (rv >> 1) & 3;
            uint32_t offa = (uint32_t)(rv * 64 + (((0 + lchk) ^ sw) << 4));
            uint32_t offb = (uint32_t)(rv * 64 + (((2 + lchk) ^ sw) << 4));
            ldsm4t(vha, uVH + offa);
            ldsm4t(vla, uVL + offa);
            ldsm4t(vhb, uVH + offb);
            ldsm4t(vlb, uVL + offb);
        }
        uint32_t ph[4], pl[4];
        hilo2(sc[2 * kt][0],     sc[2 * kt][1],     ph[0], pl[0]);
        hilo2(sc[2 * kt][2],     sc[2 * kt][3],     ph[1], pl[1]);
        hilo2(sc[2 * kt + 1][0], sc[2 * kt + 1][1], ph[2], pl[2]);
        hilo2(sc[2 * kt + 1][2], sc[2 * kt + 1][3], ph[3], pl[3]);
        mma16816b(out[0], ph, vha[0], vha[1]);
        mma16816b(out[0], pl, vha[0], vha[1]);
        mma16816b(out[0], ph, vla[0], vla[1]);
        mma16816b(out[1], ph, vha[2], vha[3]);
        mma16816b(out[1], pl, vha[2], vha[3]);
        mma16816b(out[1], ph, vla[2], vla[3]);
        mma16816b(out[2], ph, vhb[0], vhb[1]);
        mma16816b(out[2], pl, vhb[0], vhb[1]);
        mma16816b(out[2], ph, vlb[0], vlb[1]);
        mma16816b(out[3], ph, vhb[2], vhb[3]);
        mma16816b(out[3], pl, vhb[2], vhb[3]);
        mma16816b(out[3], ph, vlb[2], vlb[3]);
    }

    // ---- epilogue: scale by sim_t/l_t, stage, coalesced atomic scatter ----
    __syncthreads();   // all warps done reading tiles
    float* stage = (float*)SM;   // [128][33] fp32 = 16.9KB (over Q/QL/K region)
    {
        int g = lane >> 2, q = lane & 3;
        int r0 = wr * 16 + g;
        float f0 = simv[r0] * linv0;
        float f1 = simv[r0 + 8] * linv1;
#pragma unroll
        for (int nt = 0; nt < 4; nt++) {
            int c = nt * 8 + 2 * q;
            stage[r0 * 33 + c]           = out[nt][0] * f0;
            stage[r0 * 33 + c + 1]       = out[nt][1] * f0;
            stage[(r0 + 8) * 33 + c]     = out[nt][2] * f1;
            stage[(r0 + 8) * 33 + c + 1] = out[nt][3] * f1;
        }
    }
    __syncthreads();
#pragma unroll 4
    for (int i = 0; i < 16; i++) {
        int tt = i * 8 + wr;
        atomicAdd(&g_acc[((size_t)b * NHW + idxs[tt]) * NC + h * NDH + lane],
                  stage[tt * 33 + lane]);
    }
}

// =====================================================================
// Kernel 5: transpose accumulator (B, HW, C) -> out (B, C, HW)
// =====================================================================
__global__ void __launch_bounds__(256) transpose_kernel(float* __restrict__ out) {
    __shared__ float tile[32][33];
    const int b  = blockIdx.z;
    const int n0 = blockIdx.x * 32;
    const int c0 = blockIdx.y * 32;
    const int tx = threadIdx.x, ty = threadIdx.y;
#pragma unroll
    for (int j = 0; j < 32; j += 8)
        tile[ty + j][tx] = g_acc[((size_t)b * NHW + n0 + ty + j) * NC + c0 + tx];
    __syncthreads();
#pragma unroll
    for (int j = 0; j < 32; j += 8)
        out[((size_t)b * NC + c0 + ty + j) * NHW + n0 + tx] = tile[tx][ty + j];
}

// =====================================================================
extern "C" void kernel_launch(void* const* d_in, const int* in_sizes, int n_in,
                              void* d_out, int out_size) {
    const float* x    = (const float*)d_in[0];
    const float* aff  = (const float*)d_in[1];
    const float* lnw  = (const float*)d_in[2];
    const float* lnb  = (const float*)d_in[3];
    const float* wq   = (const float*)d_in[4];
    const float* wk   = (const float*)d_in[5];
    const float* wv   = (const float*)d_in[6];
    float* out = (float*)d_out;

    cudaFuncSetAttribute(tc_gemm_kernel,
                         cudaFuncAttributeMaxDynamicSharedMemorySize, 2 * STAGEB);
    cudaFuncSetAttribute(attn_kernel,
                         cudaFuncAttributeMaxDynamicSharedMemorySize, ATT_SMEM);

    ln_stats_kernel<<<(NB * NHW) / 256, 256>>>(x);
    xsplit_kernel<<<dim3(NHW / 32, NC / 32, NB), dim3(32, 8)>>>(x, lnw, lnb);
    wsplit_kernel<<<MTOT, 256>>>(wq, wk, wv);
    topk_kernel<<<NB * NS, 512>>>(aff);
    tc_gemm_kernel<<<dim3(MTOT / 128, NHW / 128, NB), 256, 2 * STAGEB>>>();
    attn_kernel<<<dim3(NS, NHEADS, NB), 256, ATT_SMEM>>>();
    transpose_kernel<<<dim3(NHW / 32, NC / 32, NB), dim3(32, 8)>>>(out);
}

// round 14
// speedup vs baseline: 2.8964x; 1.0606x over previous
#include <cuda_runtime.h>
#include <cuda_bf16.h>
#include <cstdint>
#include <math.h>

// ---------------- problem constants ----------------
constexpr int NB     = 2;
constexpr int NC     = 256;     // channels (= QK)
constexpr int NHW    = 16384;   // H*W
constexpr int NS     = 256;     // superpixels
constexpr int NT     = 128;     // top-k
constexpr int NHEADS = 8;
constexpr int NDH    = 32;      // head dim
constexpr int MTOT   = 768;     // q(256) + k(256) + v(256)
constexpr float EPSV      = 1e-5f;
constexpr float ATT_SCALE = 0.17677669529663687f;  // 1/sqrt(32)

// ---------------- scratch (device globals; no allocations allowed) ----------
__device__ __nv_bfloat16 g_ybh[(size_t)NB * NHW * MTOT]; // qkv hi, n-major
__device__ __nv_bfloat16 g_ybl[(size_t)NB * NHW * MTOT]; // qkv lo
__device__ float  g_acc[(size_t)NB * NHW * NC];          // output accumulator (n-major)
__device__ float  g_sims[NB * NS * NT];
__device__ int    g_idx [NB * NS * NT];
__device__ __nv_bfloat16 g_xh[(size_t)NB * NHW * NC];    // ln(x) hi, [b][n][c]
__device__ __nv_bfloat16 g_xl[(size_t)NB * NHW * NC];    // ln(x) lo
__device__ __nv_bfloat16 g_wh[MTOT * NC];                // stacked W hi
__device__ __nv_bfloat16 g_wl[MTOT * NC];                // stacked W lo

// ---------------- PTX helpers (baseline ISA only, valid on compute_103) ----
__device__ __forceinline__ uint32_t smem_u32(const void* p) {
    uint32_t a;
    asm("{ .reg .u64 t; cvta.to.shared.u64 t, %1; cvt.u32.u64 %0, t; }" : "=r"(a) : "l"(p));
    return a;
}
__device__ __forceinline__ void ldsm4(uint32_t* r, uint32_t addr) {
    asm volatile("ldmatrix.sync.aligned.m8n8.x4.shared.b16 {%0,%1,%2,%3}, [%4];"
                 : "=r"(r[0]), "=r"(r[1]), "=r"(r[2]), "=r"(r[3]) : "r"(addr));
}
__device__ __forceinline__ void ldsm4t(uint32_t* r, uint32_t addr) {
    asm volatile("ldmatrix.sync.aligned.m8n8.x4.trans.shared.b16 {%0,%1,%2,%3}, [%4];"
                 : "=r"(r[0]), "=r"(r[1]), "=r"(r[2]), "=r"(r[3]) : "r"(addr));
}
__device__ __forceinline__ void mma16816(float* d, const uint32_t* a, const uint32_t* b) {
    asm volatile("mma.sync.aligned.m16n8k16.row.col.f32.bf16.bf16.f32 "
                 "{%0,%1,%2,%3}, {%4,%5,%6,%7}, {%8,%9}, {%0,%1,%2,%3};"
                 : "+f"(d[0]), "+f"(d[1]), "+f"(d[2]), "+f"(d[3])
                 : "r"(a[0]), "r"(a[1]), "r"(a[2]), "r"(a[3]), "r"(b[0]), "r"(b[1]));
}
__device__ __forceinline__ void mma16816b(float* d, const uint32_t* a, uint32_t b0, uint32_t b1) {
    asm volatile("mma.sync.aligned.m16n8k16.row.col.f32.bf16.bf16.f32 "
                 "{%0,%1,%2,%3}, {%4,%5,%6,%7}, {%8,%9}, {%0,%1,%2,%3};"
                 : "+f"(d[0]), "+f"(d[1]), "+f"(d[2]), "+f"(d[3])
                 : "r"(a[0]), "r"(a[1]), "r"(a[2]), "r"(a[3]), "r"(b0), "r"(b1));
}
__device__ __forceinline__ void cp16(uint32_t dst, const void* src) {
    asm volatile("{ .reg .u64 g; cvta.to.global.u64 g, %1; cp.async.ca.shared.global [%0], [g], 16; }"
                 :: "r"(dst), "l"(src) : "memory");
}
#define CP_COMMIT() asm volatile("cp.async.commit_group;" ::: "memory")
template <int N>
__device__ __forceinline__ void cp_wait() {
    asm volatile("cp.async.wait_group %0;" :: "n"(N) : "memory");
}
__device__ __forceinline__ void hilo2(float a, float b, uint32_t& hi, uint32_t& lo) {
    __nv_bfloat16 ah = __float2bfloat16_rn(a), bh = __float2bfloat16_rn(b);
    __nv_bfloat162 hp; hp.x = ah; hp.y = bh;
    __nv_bfloat162 lp;
    lp.x = __float2bfloat16_rn(a - __bfloat162float(ah));
    lp.y = __float2bfloat16_rn(b - __bfloat162float(bh));
    hi = *(uint32_t*)&hp;
    lo = *(uint32_t*)&lp;
}

// =====================================================================
// Kernel 1: fused LayerNorm + transpose + bf16 hi/lo split.
//   Block = 64 pixels x 256 channels staged once in smem (stride-65 pad).
// =====================================================================
constexpr int LNS = 256 * 65 * 4;   // 66560 B
__global__ void __launch_bounds__(256) lnsplit_kernel(const float* __restrict__ x,
                                                      const float* __restrict__ lw,
                                                      const float* __restrict__ lb) {
    extern __shared__ float T[];            // [256][65]
    __shared__ float ps[4][64], pss[4][64], muv[64], invv[64];
    __shared__ float wv[256], bv[256];
    const int tid = threadIdx.x;
    const int p0 = blockIdx.x * 64;
    const int b  = p0 >> 14;
    const int n0 = p0 & (NHW - 1);
    wv[tid] = lw[tid]; bv[tid] = lb[tid];

    const float* xb = x + (size_t)b * NC * NHW + n0;
#pragma unroll
    for (int i = tid; i < 256 * 16; i += 256) {
        int c = i >> 4, f4 = i & 15;
        float4 v = *(const float4*)(xb + (size_t)c * NHW + f4 * 4);
        float* dst = &T[c * 65 + f4 * 4];
        dst[0] = v.x; dst[1] = v.y; dst[2] = v.z; dst[3] = v.w;
    }
    __syncthreads();
    {
        int p = tid & 63, q = tid >> 6;
        float s = 0.f, ss = 0.f;
#pragma unroll 8
        for (int c = q * 64; c < q * 64 + 64; c++) {
            float v = T[c * 65 + p];
            s += v; ss += v * v;
        }
        ps[q][p] = s; pss[q][p] = ss;
    }
    __syncthreads();
    if (tid < 64) {
        float s  = ps[0][tid] + ps[1][tid] + ps[2][tid] + ps[3][tid];
        float ss = pss[0][tid] + pss[1][tid] + pss[2][tid] + pss[3][tid];
        float mu = s * (1.0f / NC);
        muv[tid] = mu;
        invv[tid] = rsqrtf(ss * (1.0f / NC) - mu * mu + EPSV);
    }
    __syncthreads();
    const int c = tid;
    const float w = wv[c], bi = bv[c];
#pragma unroll 4
    for (int k = 0; k < 64; k++) {
        float v = (T[c * 65 + k] - muv[k]) * invv[k] * w + bi;
        __nv_bfloat16 hi = __float2bfloat16_rn(v);
        size_t o = ((size_t)b * NHW + n0 + k) * NC + c;
        g_xh[o] = hi;
        g_xl[o] = __float2bfloat16_rn(v - __bfloat162float(hi));
    }
}

// =====================================================================
// Kernel 1c: split stacked W (wq;wk;wv) into bf16 hi/lo.
// =====================================================================
__global__ void __launch_bounds__(256) wsplit_kernel(const float* __restrict__ wq,
                                                     const float* __restrict__ wk,
                                                     const float* __restrict__ wv) {
    int m = blockIdx.x, c = threadIdx.x;
    const float* src = (m < 256) ? (wq + (size_t)m * NC)
                     : (m < 512) ? (wk + (size_t)(m - 256) * NC)
                                 : (wv + (size_t)(m - 512) * NC);
    float v = src[c];
    __nv_bfloat16 hi = __float2bfloat16_rn(v);
    __nv_bfloat16 lo = __float2bfloat16_rn(v - __bfloat162float(hi));
    g_wh[(size_t)m * NC + c] = hi;
    g_wl[(size_t)m * NC + c] = lo;
}

// =====================================================================
// Kernel 2: exact top-128 per row (warp-aggregated radix, float4 sweeps).
// =====================================================================
__device__ __forceinline__ unsigned f2k(float f) {
    unsigned u = __float_as_uint(f);
    return (u & 0x80000000u) ? ~u : (u | 0x80000000u);
}
constexpr int TCAP = 4096;

__global__ void __launch_bounds__(512) topk_kernel(const float* __restrict__ aff) {
    const int row = blockIdx.x;
    const float* a = aff + (size_t)row * NHW;
    const float4* a4 = (const float4*)a;
    const int tid = threadIdx.x, lane = tid & 31;

    __shared__ unsigned hist[256];
    __shared__ float candV[TCAP];
    __shared__ int   candI[TCAP];
    __shared__ unsigned sh_digit, sh_rem;
    __shared__ int cnt, nc, eqcnt;
    __shared__ int eqlist[64];

    for (int i = tid; i < 256; i += 512) hist[i] = 0;
    if (tid == 0) { cnt = 0; nc = 0; eqcnt = 0; }
    __syncthreads();

    // ---- pass 1: top-byte histogram (float4, warp-aggregated) ----
    for (int i = tid; i < NHW / 4; i += 512) {
        float4 v = a4[i];
        float vals[4] = {v.x, v.y, v.z, v.w};
#pragma unroll
        for (int j = 0; j < 4; j++) {
            unsigned byte = f2k(vals[j]) >> 24;
            unsigned m = __match_any_sync(0xFFFFFFFFu, byte);
            if ((int)(__ffs(m) - 1) == lane) atomicAdd(&hist[byte], __popc(m));
        }
    }
    __syncthreads();
    if (tid == 0) {
        unsigned r = NT;
        int d = 255;
        for (; d > 0; d--) {
            unsigned c = hist[d];
            if (c >= r) break;
            r -= c;
        }
        sh_digit = (unsigned)d;
        sh_rem = r;
    }
    __syncthreads();
    const unsigned dtop = sh_digit;
    unsigned rem = sh_rem;

    float* so = g_sims + (size_t)row * NT;
    int*   io = g_idx  + (size_t)row * NT;

    // ---- sweep: direct-emit (> pivot byte), compact candidates (==) ----
    for (int i = tid; i < NHW / 4; i += 512) {
        float4 v = a4[i];
        float vals[4] = {v.x, v.y, v.z, v.w};
#pragma unroll
        for (int j = 0; j < 4; j++) {
            unsigned byte = f2k(vals[j]) >> 24;
            if (byte > dtop) {
                int p = atomicAdd(&cnt, 1);
                so[p] = vals[j]; io[p] = 4 * i + j;
            } else if (byte == dtop) {
                int q = atomicAdd(&nc, 1);
                if (q < TCAP) { candV[q] = vals[j]; candI[q] = 4 * i + j; }
            }
        }
    }
    __syncthreads();

    unsigned prefix  = dtop << 24;
    unsigned prefmask = 0xFF000000u;
    const bool incache = (nc <= TCAP);
    const int ncand = incache ? nc : 0;

    for (int shift = 16; shift >= 0; shift -= 8) {
        for (int i = tid; i < 256; i += 512) hist[i] = 0;
        __syncthreads();
        if (incache) {
            for (int j = tid; j < ncand; j += 512) {
                unsigned key = f2k(candV[j]);
                if ((key & prefmask) == prefix) {
                    unsigned byte = (key >> shift) & 255u;
                    unsigned m = __match_any_sync(__activemask(), byte);
                    if ((int)(__ffs(m) - 1) == lane) atomicAdd(&hist[byte], __popc(m));
                }
            }
        } else {
            for (int i = tid; i < NHW; i += 512) {
                unsigned key = f2k(a[i]);
                if ((key & prefmask) == prefix) {
                    unsigned byte = (key >> shift) & 255u;
                    unsigned m = __match_any_sync(__activemask(), byte);
                    if ((int)(__ffs(m) - 1) == lane) atomicAdd(&hist[byte], __popc(m));
                }
            }
        }
        __syncthreads();
        if (tid == 0) {
            unsigned r = rem;
            int d = 255;
            for (; d > 0; d--) {
                unsigned c = hist[d];
                if (c >= r) break;
                r -= c;
            }
            sh_digit = (unsigned)d;
            sh_rem = r;
        }
        __syncthreads();
        prefix   |= (sh_digit << shift);
        prefmask |= (0xFFu << shift);
        rem = sh_rem;
        __syncthreads();
    }

    const unsigned thresh = prefix;
    if (incache) {
        for (int j = tid; j < ncand; j += 512) {
            unsigned key = f2k(candV[j]);
            if (key > thresh) {
                int p = atomicAdd(&cnt, 1);
                so[p] = candV[j]; io[p] = candI[j];
            } else if (key == thresh) {
                int p = atomicAdd(&eqcnt, 1);
                if (p < 64) eqlist[p] = candI[j];
            }
        }
    } else {
        for (int i = tid; i < NHW; i += 512) {
            float v = a[i];
            unsigned key = f2k(v);
            if (key > thresh && (key >> 24) == dtop) {
                int p = atomicAdd(&cnt, 1);
                so[p] = v; io[p] = i;
            } else if (key == thresh) {
                int p = atomicAdd(&eqcnt, 1);
                if (p < 64) eqlist[p] = i;
            }
        }
    }
    __syncthreads();
    if (tid == 0) {
        int need = NT - cnt;
        int m = eqcnt < 64 ? eqcnt : 64;
        for (int i = 1; i < m; i++) {
            int key = eqlist[i]; int j = i - 1;
            while (j >= 0 && eqlist[j] > key) { eqlist[j + 1] = eqlist[j]; j--; }
            eqlist[j + 1] = key;
        }
        float tv = __uint_as_float((thresh & 0x80000000u) ? (thresh & 0x7FFFFFFFu) : ~thresh);
        for (int r = 0; r < need && r < m; r++) {
            so[cnt + r] = tv;
            io[cnt + r] = eqlist[r];
        }
    }
}

// =====================================================================
// Kernel 3: bf16-split QKV GEMM on HMMA, cp.async double-buffered.
// =====================================================================
constexpr int TILEB = 8192;
constexpr int STAGEB = 4 * TILEB;
__global__ void __launch_bounds__(256) tc_gemm_kernel() {
    extern __shared__ __align__(128) char smem_raw[];

    const int m0 = blockIdx.x * 128;
    const int n0 = blockIdx.y * 128;
    const int b  = blockIdx.z;
    const int tid = threadIdx.x;
    const int wrp = tid >> 5, lane = tid & 31;
    const int wm = wrp >> 2, wn = wrp & 3;

    const uint32_t sbase = smem_u32(smem_raw);
    const size_t xbase = (size_t)b * NHW * NC;

    const int lj = lane >> 3, lr = lane & 7;
    const int a_row = wm * 64 + (lj & 1) * 8 + lr;
    const int a_j0  = lj >> 1;
    const int b_row = wn * 32 + (lj >> 1) * 8 + lr;
    const int b_j0  = lj & 1;

    float acc[4][4][4];
#pragma unroll
    for (int i = 0; i < 4; i++)
#pragma unroll
        for (int j = 0; j < 4; j++)
#pragma unroll
            for (int r = 0; r < 4; r++) acc[i][j][r] = 0.f;

    auto load_stage = [&](int stage, int k0) {
        const uint32_t sb = sbase + stage * STAGEB;
#pragma unroll
        for (int i = 0; i < 8; i++) {
            const int arr = i >> 1;
            const int rem = ((i & 1) << 8) + tid;
            const int r = rem >> 2, c = rem & 3;
            uint32_t dst = sb + arr * TILEB + r * 64 + ((c ^ ((r >> 1) & 3)) << 4);
            const __nv_bfloat16* src;
            if (arr == 0)      src = g_wh + (size_t)(m0 + r) * NC + k0;
            else if (arr == 1) src = g_wl + (size_t)(m0 + r) * NC + k0;
            else if (arr == 2) src = g_xh + xbase + (size_t)(n0 + r) * NC + k0;
            else               src = g_xl + xbase + (size_t)(n0 + r) * NC + k0;
            cp16(dst, src + c * 8);
        }
        CP_COMMIT();
    };

    load_stage(0, 0);

    for (int kc = 0; kc < 8; kc++) {
        if (kc < 7) load_stage((kc + 1) & 1, (kc + 1) * 32);
        if (kc < 7) cp_wait<1>(); else cp_wait<0>();
        __syncthreads();

        const uint32_t sb = sbase + (kc & 1) * STAGEB;
        const uint32_t bAh = sb, bAl = sb + TILEB, bBh = sb + 2 * TILEB, bBl = sb + 3 * TILEB;

#pragma unroll
        for (int ks = 0; ks < 2; ks++) {
            uint32_t bh[2][4], bl[2][4];
#pragma unroll
            for (int bt = 0; bt < 2; bt++) {
                int r = b_row + bt * 16;
                int j = b_j0 + ks * 2;
                uint32_t off = (uint32_t)(r * 64 + ((j ^ ((r >> 1) & 3)) << 4));
                ldsm4(bh[bt], bBh + off);
                ldsm4(bl[bt], bBl + off);
            }
#pragma unroll
            for (int mt = 0; mt < 4; mt++) {
                int r = a_row + mt * 16;
                int j = a_j0 + ks * 2;
                uint32_t off = (uint32_t)(r * 64 + ((j ^ ((r >> 1) & 3)) << 4));
                uint32_t ah[4], al[4];
                ldsm4(ah, bAh + off);
                ldsm4(al, bAl + off);
#pragma unroll
                for (int bt = 0; bt < 2; bt++)
#pragma unroll
                    for (int sub = 0; sub < 2; sub++) {
                        int nt = bt * 2 + sub;
                        mma16816(acc[mt][nt], ah, &bh[bt][sub * 2]);
                        mma16816(acc[mt][nt], al, &bh[bt][sub * 2]);
                        mma16816(acc[mt][nt], ah, &bl[bt][sub * 2]);
                    }
            }
        }
        __syncthreads();
    }

    float* ep = (float*)smem_raw;
    const int g = lane >> 2, q = lane & 3;
    for (int ci = 0; ci < 4; ci++) {
        if (wn == ci) {
#pragma unroll
            for (int mt = 0; mt < 4; mt++)
#pragma unroll
                for (int nt = 0; nt < 4; nt++) {
                    int nn = nt * 8 + 2 * q;
                    int m  = wm * 64 + mt * 16 + g;
                    ep[nn * 132 + m]           = acc[mt][nt][0];
                    ep[(nn + 1) * 132 + m]     = acc[mt][nt][1];
                    ep[nn * 132 + m + 8]       = acc[mt][nt][2];
                    ep[(nn + 1) * 132 + m + 8] = acc[mt][nt][3];
                }
        }
        __syncthreads();

        int nrow = tid >> 3, seg = (tid & 7) * 16;
        int n = n0 + ci * 32 + nrow;
        const float* src = ep + nrow * 132 + seg;
        size_t yo = ((size_t)b * NHW + n) * MTOT + m0 + seg;
        __nv_bfloat16 hb[16], lb[16];
#pragma unroll
        for (int i = 0; i < 16; i++) {
            float v = src[i];
            hb[i] = __float2bfloat16_rn(v);
            lb[i] = __float2bfloat16_rn(v - __bfloat162float(hb[i]));
        }
        *(uint4*)(g_ybh + yo)     = *(uint4*)&hb[0];
        *(uint4*)(g_ybh + yo + 8) = *(uint4*)&hb[8];
        *(uint4*)(g_ybl + yo)     = *(uint4*)&lb[0];
        *(uint4*)(g_ybl + yo + 8) = *(uint4*)&lb[8];
        if (m0 >= 512) {
            float* adst = g_acc + ((size_t)b * NHW + n) * NC + (m0 - 512) + seg;
#pragma unroll
            for (int i = 0; i < 16; i += 4)
                *(float4*)(adst + i) = make_float4(src[i], src[i + 1], src[i + 2], src[i + 3]);
        }
        __syncthreads();
    }
}

// =====================================================================
// Kernel 4: HMMA attention per (s, head, b) tile.
// =====================================================================
constexpr int ATT_SMEM = 50176;
__global__ void __launch_bounds__(256) attn_kernel() {
    extern __shared__ __align__(128) char SM[];
    const int s = blockIdx.x, h = blockIdx.y, b = blockIdx.z;
    const int tid = threadIdx.x, lane = tid & 31, wr = tid >> 5;

    int*   idxs = (int*)(SM + 49152);
    float* simv = (float*)(SM + 49664);

    if (tid < NT) {
        const int gi = (b * NS + s) * NT + tid;
        idxs[tid] = g_idx[gi];
        simv[tid] = g_sims[gi];
    }
    __syncthreads();

    const uint32_t tb = smem_u32(SM);
    const uint32_t uQH = tb, uQL = tb + 8192, uKH = tb + 16384, uKL = tb + 24576,
                   uVH = tb + 32768, uVL = tb + 40960;

#pragma unroll
    for (int i = 0; i < 2; i++) {
        int r = i * 64 + (tid >> 2), c = tid & 3;
        uint32_t swoff = (uint32_t)(r * 64 + ((c ^ ((r >> 1) & 3)) << 4));
        size_t rowb = ((size_t)b * NHW + idxs[r]) * MTOT + h * 32 + c * 8;
#pragma unroll
        for (int ar = 0; ar < 3; ar++) {
            cp16(tb + ar * 16384 + swoff,        g_ybh + rowb + ar * 256);
            cp16(tb + ar * 16384 + 8192 + swoff, g_ybl + rowb + ar * 256);
        }
    }
    CP_COMMIT();
    cp_wait<0>();
    __syncthreads();

    const int lrow = ((lane >> 3) & 1) * 8 + (lane & 7);
    const int lchk = lane >> 4;

    float sc[16][4];
#pragma unroll
    for (int nt = 0; nt < 16; nt++)
#pragma unroll
        for (int j = 0; j < 4; j++) sc[nt][j] = 0.f;

#pragma unroll
    for (int kc = 0; kc < 2; kc++) {
        int chunk = 2 * kc + lchk;
        int rq = wr * 16 + lrow;
        uint32_t offq = (uint32_t)(rq * 64 + ((chunk ^ ((rq >> 1) & 3)) << 4));
        uint32_t aqh[4], aql[4];
        ldsm4(aqh, uQH + offq);
        ldsm4(aql, uQL + offq);
#pragma unroll
        for (int un = 0; un < 8; un++) {
            int rk = un * 16 + lrow;
            uint32_t offk = (uint32_t)(rk * 64 + ((chunk ^ ((rk >> 1) & 3)) << 4));
            uint32_t kh4[4], kl4[4];
            ldsm4(kh4, uKH + offk);
            ldsm4(kl4, uKL + offk);
#pragma unroll
            for (int sub = 0; sub < 2; sub++) {
                float* d = sc[un * 2 + sub];
                mma16816b(d, aqh, kh4[sub], kh4[sub + 2]);
                mma16816b(d, aql, kh4[sub], kh4[sub + 2]);
                mma16816b(d, aqh, kl4[sub], kl4[sub + 2]);
            }
        }
    }

    float m0 = -1e30f, m1 = -1e30f;
#pragma unroll
    for (int nt = 0; nt < 16; nt++) {
        m0 = fmaxf(m0, fmaxf(sc[nt][0], sc[nt][1]));
        m1 = fmaxf(m1, fmaxf(sc[nt][2], sc[nt][3]));
    }
    m0 = fmaxf(m0, __shfl_xor_sync(0xFFFFFFFFu, m0, 1));
    m0 = fmaxf(m0, __shfl_xor_sync(0xFFFFFFFFu, m0, 2));
    m1 = fmaxf(m1, __shfl_xor_sync(0xFFFFFFFFu, m1, 1));
    m1 = fmaxf(m1, __shfl_xor_sync(0xFFFFFFFFu, m1, 2));
    float s0 = 0.f, s1 = 0.f;
#pragma unroll
    for (int nt = 0; nt < 16; nt++) {
        sc[nt][0] = __expf((sc[nt][0] - m0) * ATT_SCALE);
        sc[nt][1] = __expf((sc[nt][1] - m0) * ATT_SCALE);
        sc[nt][2] = __expf((sc[nt][2] - m1) * ATT_SCALE);
        sc[nt][3] = __expf((sc[nt][3] - m1) * ATT_SCALE);
        s0 += sc[nt][0] + sc[nt][1];
        s1 += sc[nt][2] + sc[nt][3];
    }
    s0 += __shfl_xor_sync(0xFFFFFFFFu, s0, 1);
    s0 += __shfl_xor_sync(0xFFFFFFFFu, s0, 2);
    s1 += __shfl_xor_sync(0xFFFFFFFFu, s1, 1);
    s1 += __shfl_xor_sync(0xFFFFFFFFu, s1, 2);
    const float linv0 = 1.0f / s0, linv1 = 1.0f / s1;

#pragma unroll
    for (int nt = 0; nt < 16; nt++) {
        int u0 = nt * 8 + 2 * (lane & 3);
        float su0 = simv[u0], su1 = simv[u0 + 1];
        sc[nt][0] *= su0; sc[nt][1] *= su1;
        sc[nt][2] *= su0; sc[nt][3] *= su1;
    }

    float out[4][4];
#pragma unroll
    for (int nt = 0; nt < 4; nt++)
#pragma unroll
        for (int j = 0; j < 4; j++) out[nt][j] = 0.f;

#pragma unroll
    for (int kt = 0; kt < 8; kt++) {
        uint32_t vha[4], vla[4], vhb[4], vlb[4];
        {
            int rv = kt * 16 + lrow;
            int sw = (rv >> 1) & 3;
            uint32_t offa = (uint32_t)(rv * 64 + (((0 + lchk) ^ sw) << 4));
            uint32_t offb = (uint32_t)(rv * 64 + (((2 + lchk) ^ sw) << 4));
            ldsm4t(vha, uVH + offa);
            ldsm4t(vla, uVL + offa);
            ldsm4t(vhb, uVH + offb);
            ldsm4t(vlb, uVL + offb);
        }
        uint32_t ph[4], pl[4];
        hilo2(sc[2 * kt][0],     sc[2 * kt][1],     ph[0], pl[0]);
        hilo2(sc[2 * kt][2],     sc[2 * kt][3],     ph[1], pl[1]);
        hilo2(sc[2 * kt + 1][0], sc[2 * kt + 1][1], ph[2], pl[2]);
        hilo2(sc[2 * kt + 1][2], sc[2 * kt + 1][3], ph[3], pl[3]);
        mma16816b(out[0], ph, vha[0], vha[1]);
        mma16816b(out[0], pl, vha[0], vha[1]);
        mma16816b(out[0], ph, vla[0], vla[1]);
        mma16816b(out[1], ph, vha[2], vha[3]);
        mma16816b(out[1], pl, vha[2], vha[3]);
        mma16816b(out[1], ph, vla[2], vla[3]);
        mma16816b(out[2], ph, vhb[0], vhb[1]);
        mma16816b(out[2], pl, vhb[0], vhb[1]);
        mma16816b(out[2], ph, vlb[0], vlb[1]);
        mma16816b(out[3], ph, vhb[2], vhb[3]);
        mma16816b(out[3], pl, vhb[2], vhb[3]);
        mma16816b(out[3], ph, vlb[2], vlb[3]);
    }

    __syncthreads();
    float* stage = (float*)SM;
    {
        int g = lane >> 2, q = lane & 3;
        int r0 = wr * 16 + g;
        float f0 = simv[r0] * linv0;
        float f1 = simv[r0 + 8] * linv1;
#pragma unroll
        for (int nt = 0; nt < 4; nt++) {
            int c = nt * 8 + 2 * q;
            stage[r0 * 33 + c]           = out[nt][0] * f0;
            stage[r0 * 33 + c + 1]       = out[nt][1] * f0;
            stage[(r0 + 8) * 33 + c]     = out[nt][2] * f1;
            stage[(r0 + 8) * 33 + c + 1] = out[nt][3] * f1;
        }
    }
    __syncthreads();
#pragma unroll 4
    for (int i = 0; i < 16; i++) {
        int tt = i * 8 + wr;
        atomicAdd(&g_acc[((size_t)b * NHW + idxs[tt]) * NC + h * NDH + lane],
                  stage[tt * 33 + lane]);
    }
}

// =====================================================================
// Kernel 5: transpose accumulator (B, HW, C) -> out (B, C, HW)
// =====================================================================
__global__ void __launch_bounds__(256) transpose_kernel(float* __restrict__ out) {
    __shared__ float tile[32][33];
    const int b  = blockIdx.z;
    const int n0 = blockIdx.x * 32;
    const int c0 = blockIdx.y * 32;
    const int tx = threadIdx.x, ty = threadIdx.y;
#pragma unroll
    for (int j = 0; j < 32; j += 8)
        tile[ty + j][tx] = g_acc[((size_t)b * NHW + n0 + ty + j) * NC + c0 + tx];
    __syncthreads();
#pragma unroll
    for (int j = 0; j < 32; j += 8)
        out[((size_t)b * NC + c0 + ty + j) * NHW + n0 + tx] = tile[tx][ty + j];
}

// =====================================================================
extern "C" void kernel_launch(void* const* d_in, const int* in_sizes, int n_in,
                              void* d_out, int out_size) {
    const float* x    = (const float*)d_in[0];
    const float* aff  = (const float*)d_in[1];
    const float* lnw  = (const float*)d_in[2];
    const float* lnb  = (const float*)d_in[3];
    const float* wq   = (const float*)d_in[4];
    const float* wk   = (const float*)d_in[5];
    const float* wv   = (const float*)d_in[6];
    float* out = (float*)d_out;

    cudaFuncSetAttribute(tc_gemm_kernel,
                         cudaFuncAttributeMaxDynamicSharedMemorySize, 2 * STAGEB);
    cudaFuncSetAttribute(attn_kernel,
                         cudaFuncAttributeMaxDynamicSharedMemorySize, ATT_SMEM);
    cudaFuncSetAttribute(lnsplit_kernel,
                         cudaFuncAttributeMaxDynamicSharedMemorySize, LNS);

    lnsplit_kernel<<<(NB * NHW) / 64, 256, LNS>>>(x, lnw, lnb);
    wsplit_kernel<<<MTOT, 256>>>(wq, wk, wv);
    topk_kernel<<<NB * NS, 512>>>(aff);
    tc_gemm_kernel<<<dim3(MTOT / 128, NHW / 128, NB), 256, 2 * STAGEB>>>();
    attn_kernel<<<dim3(NS, NHEADS, NB), 256, ATT_SMEM>>>();
    transpose_kernel<<<dim3(NHW / 32, NC / 32, NB), dim3(32, 8)>>>(out);
}